// round 9
// baseline (speedup 1.0000x reference)
#include <cuda_runtime.h>
#include <cuda_bf16.h>
#include <stdint.h>
#include <math.h>

// ---------------------------------------------------------------------------
// Problem constants
// ---------------------------------------------------------------------------
#define H_SP 50
#define W_SP 75
#define N_SP 3750
#define R_ROIS 1000
#define C_MID 490
#define FC1_DIM 2048
#define LOC_DIM 324
#define SCORE_DIM 81
#define K1 30720            // conv1 GEMM K (15 taps * 2048 ic)
#define K2 7680             // conv2 GEMM K (2 branches * 15 taps * 256 ic)
#define OC1 512
#define KFC 512             // fc1 K (490 padded)
#define NPAD 1024           // roi rows padded

// smem staging: Ahi(128r) Alo(128r) Bhi(64r) Blo(64r), rows of 32 bf16, pad to 80B
#define ROWB  80
#define AHI_OFF 0
#define ALO_OFF (128 * ROWB)        // 10240
#define BHI_OFF (256 * ROWB)        // 20480
#define BLO_OFF (320 * ROWB)        // 25600
#define STAGE   (384 * ROWB)        // 30720
#define DYN_SMEM (2 * STAGE)        // 61440 (double buffer)

// ---------------------------------------------------------------------------
// Scratch (device globals, zero-initialized at load; padding regions never
// written so they stay zero)
// ---------------------------------------------------------------------------
__device__ __nv_bfloat16 g_w1hi[OC1 * K1], g_w1lo[OC1 * K1];
__device__ __nv_bfloat16 g_w2hi[OC1 * K2], g_w2lo[OC1 * K2];   // rows 490..511 zero
__device__ __nv_bfloat16 g_xthi[N_SP * 2048], g_xtlo[N_SP * 2048];
__device__ __nv_bfloat16 g_y1thi[N_SP * 512], g_y1tlo[N_SP * 512];
__device__ float g_hT[N_SP * C_MID];
__device__ __nv_bfloat16 g_flathi[NPAD * KFC], g_flatlo[NPAD * KFC];     // cols 490+ zero
__device__ __nv_bfloat16 g_fcwhi[FC1_DIM * KFC], g_fcwlo[FC1_DIM * KFC];
__device__ __nv_bfloat16 g_fc1hi[NPAD * FC1_DIM], g_fc1lo[NPAD * FC1_DIM];
__device__ __nv_bfloat16 g_hwhi[512 * FC1_DIM], g_hwlo[512 * FC1_DIM];   // rows 405+ zero

// ---------------------------------------------------------------------------
// PTX helpers (base-sm_100-safe: cp.async / ldmatrix / mma.sync)
// ---------------------------------------------------------------------------
__device__ __forceinline__ uint32_t smem_u32(const void* p) {
    uint32_t a;
    asm("{ .reg .u64 t; cvta.to.shared.u64 t, %1; cvt.u32.u64 %0, t; }"
        : "=r"(a) : "l"(p));
    return a;
}
__device__ __forceinline__ void cpa16(uint32_t dst, const void* src, uint32_t sz) {
    asm volatile("cp.async.ca.shared.global [%0], [%1], 16, %2;"
                 :: "r"(dst), "l"(src), "r"(sz));
}
#define CP_COMMIT() asm volatile("cp.async.commit_group;" ::: "memory")
#define CP_WAIT1()  asm volatile("cp.async.wait_group 1;" ::: "memory")
#define CP_WAIT0()  asm volatile("cp.async.wait_group 0;" ::: "memory")

#define LDM_X4(r, addr) \
    asm volatile("ldmatrix.sync.aligned.m8n8.x4.shared.b16 {%0,%1,%2,%3}, [%4];" \
        : "=r"((r)[0]), "=r"((r)[1]), "=r"((r)[2]), "=r"((r)[3]) : "r"(addr))

#define MMA_BF16(d, a, b) \
    asm volatile("mma.sync.aligned.m16n8k16.row.col.f32.bf16.bf16.f32 " \
        "{%0,%1,%2,%3}, {%4,%5,%6,%7}, {%8,%9}, {%0,%1,%2,%3};" \
        : "+f"((d)[0]), "+f"((d)[1]), "+f"((d)[2]), "+f"((d)[3]) \
        : "r"((a)[0]), "r"((a)[1]), "r"((a)[2]), "r"((a)[3]), "r"((b)[0]), "r"((b)[1]))

// ---------------------------------------------------------------------------
// Prep kernels: layout transform + bf16 hi/lo split
// ---------------------------------------------------------------------------
__global__ void prep_w1(const float* __restrict__ wcm, const float* __restrict__ wrm,
                        __nv_bfloat16* __restrict__ hi, __nv_bfloat16* __restrict__ lo)
{
    __shared__ float tile[256 * 15];
    const int oc = blockIdx.x;
    const int t  = threadIdx.x;
    const float* src = (oc < 256) ? (wcm + (size_t)oc * K1)
                                  : (wrm + (size_t)(oc - 256) * K1);
    for (int ic0 = 0; ic0 < 2048; ic0 += 256) {
        for (int i = t; i < 256 * 15; i += 256) tile[i] = src[ic0 * 15 + i];
        __syncthreads();
        for (int j = t; j < 256 * 15; j += 256) {
            const int tap = j >> 8;
            const int ic  = j & 255;
            const float v = tile[ic * 15 + tap];
            const __nv_bfloat16 h = __float2bfloat16(v);
            const size_t idx = (size_t)oc * K1 + tap * 2048 + ic0 + ic;
            hi[idx] = h;
            lo[idx] = __float2bfloat16(v - __bfloat162float(h));
        }
        __syncthreads();
    }
}

__global__ void prep_w2(const float* __restrict__ wcol, const float* __restrict__ wrow,
                        __nv_bfloat16* __restrict__ hi, __nv_bfloat16* __restrict__ lo)
{
    __shared__ float tile[256 * 15];
    const int oc = blockIdx.x;   // 0..489
    const int b  = blockIdx.y;   // 0: col (1x15), 1: row (15x1)
    const int t  = threadIdx.x;
    const float* src = (b == 0 ? wcol : wrow) + (size_t)oc * 3840;
    for (int i = t; i < 256 * 15; i += 256) tile[i] = src[i];
    __syncthreads();
    for (int j = t; j < 256 * 15; j += 256) {
        const int tap = j >> 8;
        const int ic  = j & 255;
        const float v = tile[ic * 15 + tap];
        const __nv_bfloat16 h = __float2bfloat16(v);
        const size_t idx = (size_t)oc * K2 + b * 3840 + tap * 256 + ic;
        hi[idx] = h;
        lo[idx] = __float2bfloat16(v - __bfloat162float(h));
    }
}

__global__ void prep_xt(const float* __restrict__ x,
                        __nv_bfloat16* __restrict__ hi, __nv_bfloat16* __restrict__ lo)
{
    __shared__ float tile[32][33];
    const int bi = blockIdx.x;            // n tiles (118)
    const int bj = blockIdx.y;            // ic tiles (64)
    const int tx = threadIdx.x & 31;
    const int ty = threadIdx.x >> 5;      // 0..7
#pragma unroll
    for (int r = 0; r < 4; ++r) {
        const int ic = bj * 32 + ty + r * 8;
        const int n  = bi * 32 + tx;
        tile[ty + r * 8][tx] = (n < N_SP) ? x[(size_t)ic * N_SP + n] : 0.f;
    }
    __syncthreads();
#pragma unroll
    for (int r = 0; r < 4; ++r) {
        const int n  = bi * 32 + ty + r * 8;
        const int ic = bj * 32 + tx;
        if (n < N_SP) {
            const float v = tile[tx][ty + r * 8];
            const __nv_bfloat16 h = __float2bfloat16(v);
            hi[(size_t)n * 2048 + ic] = h;
            lo[(size_t)n * 2048 + ic] = __float2bfloat16(v - __bfloat162float(h));
        }
    }
}

// fc1_w [2048][490] -> [2048][512] hi/lo (pad cols zero)
__global__ void prep_fcw(const float* __restrict__ w,
                         __nv_bfloat16* __restrict__ hi, __nv_bfloat16* __restrict__ lo)
{
    const int idx = blockIdx.x * blockDim.x + threadIdx.x;
    if (idx >= FC1_DIM * C_MID) return;
    const int m = idx / C_MID;
    const int k = idx % C_MID;
    const float v = w[idx];
    const __nv_bfloat16 h = __float2bfloat16(v);
    hi[(size_t)m * KFC + k] = h;
    lo[(size_t)m * KFC + k] = __float2bfloat16(v - __bfloat162float(h));
}

// loc_w [324][2048] + score_w [81][2048] -> combined [512][2048] hi/lo
__global__ void prep_hw(const float* __restrict__ locw, const float* __restrict__ scow,
                        __nv_bfloat16* __restrict__ hi, __nv_bfloat16* __restrict__ lo)
{
    const int idx = blockIdx.x * blockDim.x + threadIdx.x;
    if (idx >= (LOC_DIM + SCORE_DIM) * FC1_DIM) return;
    const int m = idx / FC1_DIM;
    const int k = idx % FC1_DIM;
    const float v = (m < LOC_DIM) ? locw[(size_t)m * FC1_DIM + k]
                                  : scow[(size_t)(m - LOC_DIM) * FC1_DIM + k];
    const __nv_bfloat16 h = __float2bfloat16(v);
    hi[(size_t)m * FC1_DIM + k] = h;
    lo[(size_t)m * FC1_DIM + k] = __float2bfloat16(v - __bfloat162float(h));
}

// ---------------------------------------------------------------------------
// Unified GEMM on mma.sync (bf16 hi/lo 3-way split, fp32 acc).
// Block 128(M) x 64(N), K chunks of 32, cp.async double buffer, 8 warps
// in 4x2, warp tile 32x32. __launch_bounds__(256,2) -> 2 CTAs/SM.
//
// MODE 1: conv1. A=w1 [512][K1], B=XT [3750][2048], h/w shift by mBase.
//         out: y1t hi/lo bf16 [n][512] = acc + bias.
// MODE 2: conv2. A=w2 [512][K2], B=Y1T [3750][512], k-seg branch/shift.
//         out: hT fp32 [n][490] = relu(acc + b0 + b1).
// MODE 3: fc1. A=fcw [2048][512], B=flat [1024][512].
//         out: fc1 hi/lo bf16 [n][2048] = relu(acc + b0).
// MODE 4: heads. A=hw [512][2048], B=fc1 [1024][2048].
//         out: d_out (m<324 -> locs, 324..404 -> scores).
// ---------------------------------------------------------------------------
template<int MODE>
__global__ __launch_bounds__(256, 2) void mma_gemm(
    const __nv_bfloat16* __restrict__ Ahi, const __nv_bfloat16* __restrict__ Alo,
    const __nv_bfloat16* __restrict__ Bhi, const __nv_bfloat16* __restrict__ Blo,
    const float* __restrict__ bias0, const float* __restrict__ bias1,
    __nv_bfloat16* __restrict__ outhi, __nv_bfloat16* __restrict__ outlo,
    float* __restrict__ outf)
{
    constexpr int KTOT = (MODE == 1) ? K1 : (MODE == 2) ? K2 : (MODE == 3) ? KFC : FC1_DIM;
    constexpr int LDB  = (MODE == 1) ? 2048 : (MODE == 2) ? 512 : (MODE == 3) ? KFC : FC1_DIM;
    constexpr int NC   = KTOT / 32;

    extern __shared__ char smem[];
    const uint32_t sbase = smem_u32(smem);

    const int t    = threadIdx.x;
    const int wid  = t >> 5;
    const int lane = t & 31;
    const int wm   = wid >> 1;        // 0..3 (m, 32 rows each)
    const int wn   = wid & 1;         // 0..1 (n, 32 cols each)
    const int mBase = blockIdx.y * 128;
    const int nBase = blockIdx.x * 64;
    const bool mode0_c1 = (MODE == 1) && (mBase < 256);

    float acc[2][4][4];
#pragma unroll
    for (int i = 0; i < 2; ++i)
#pragma unroll
        for (int j = 0; j < 4; ++j)
#pragma unroll
            for (int q = 0; q < 4; ++q) acc[i][j][q] = 0.f;

    auto stage = [&](int buf, int c) {
        const int k0 = c * 32;
        int d = 0, coloff = k0;
        bool mode0 = false;
        if (MODE == 1) {
            const int tap = k0 >> 11;
            coloff = k0 & 2047;
            mode0  = mode0_c1;
            d = tap - 7;
        } else if (MODE == 2) {
            const int br  = (k0 >= 3840) ? 1 : 0;
            const int rem = k0 - br * 3840;
            const int tap = rem >> 8;
            coloff = br * 256 + (rem & 255);
            mode0  = (br == 1);
            d = tap - 7;
        }
        const int off = mode0 ? d * W_SP : d;
        const uint32_t sb = sbase + buf * STAGE;

#pragma unroll
        for (int v = t; v < 384; v += 256) {
            uint32_t dst;
            const char* src;
            uint32_t sz = 16;
            if (v < 128) {              // Ahi
                dst = sb + AHI_OFF + v * ROWB;
                src = (const char*)(Ahi + (size_t)(mBase + v) * KTOT + k0);
            } else if (v < 256) {       // Alo
                const int row = v - 128;
                dst = sb + ALO_OFF + row * ROWB;
                src = (const char*)(Alo + (size_t)(mBase + row) * KTOT + k0);
            } else {                    // Bhi / Blo
                const int row = (v < 320) ? (v - 256) : (v - 320);
                const int nr  = nBase + row;
                dst = sb + ((v < 320) ? BHI_OFF : BLO_OFF) + row * ROWB;
                long ns = nr;
                if (MODE <= 2) {
                    bool ok;
                    if (mode0) ok = (nr < N_SP) && ((unsigned)(nr + off) < (unsigned)N_SP);
                    else       ok = (nr < N_SP) && ((unsigned)(nr % W_SP + d) < (unsigned)W_SP);
                    ns = ok ? (long)nr + off : 0;
                    sz = ok ? 16u : 0u;
                }
                src = (const char*)(((v < 320) ? Bhi : Blo) + ns * (long)LDB + coloff);
            }
#pragma unroll
            for (int j = 0; j < 4; ++j) cpa16(dst + j * 16, src + j * 16, sz);
        }
    };

    auto compute = [&](int buf) {
        const uint32_t sb = sbase + buf * STAGE;
        const int lr = lane & 15;
        const int lc = lane >> 4;
#pragma unroll
        for (int k16 = 0; k16 < 32; k16 += 16) {
            const uint32_t kb = (uint32_t)(k16 + lc * 8) * 2;
            uint32_t a_hi[2][4], a_lo[2][4];
#pragma unroll
            for (int im = 0; im < 2; ++im) {
                const uint32_t ad = sb + (uint32_t)(wm * 32 + im * 16 + lr) * ROWB + kb;
                LDM_X4(a_hi[im], ad + AHI_OFF);
                LDM_X4(a_lo[im], ad + ALO_OFF);
            }
            uint32_t b_hi[4][2], b_lo[4][2];
#pragma unroll
            for (int ib = 0; ib < 2; ++ib) {
                const uint32_t bd = sb + (uint32_t)(wn * 32 + ib * 16 + lr) * ROWB + kb;
                uint32_t r4[4];
                LDM_X4(r4, bd + BHI_OFF);
                b_hi[2 * ib][0] = r4[0]; b_hi[2 * ib][1] = r4[2];
                b_hi[2 * ib + 1][0] = r4[1]; b_hi[2 * ib + 1][1] = r4[3];
                LDM_X4(r4, bd + BLO_OFF);
                b_lo[2 * ib][0] = r4[0]; b_lo[2 * ib][1] = r4[2];
                b_lo[2 * ib + 1][0] = r4[1]; b_lo[2 * ib + 1][1] = r4[3];
            }
#pragma unroll
            for (int im = 0; im < 2; ++im)
#pragma unroll
                for (int in = 0; in < 4; ++in) MMA_BF16(acc[im][in], a_hi[im], b_hi[in]);
#pragma unroll
            for (int im = 0; im < 2; ++im)
#pragma unroll
                for (int in = 0; in < 4; ++in) MMA_BF16(acc[im][in], a_hi[im], b_lo[in]);
#pragma unroll
            for (int im = 0; im < 2; ++im)
#pragma unroll
                for (int in = 0; in < 4; ++in) MMA_BF16(acc[im][in], a_lo[im], b_hi[in]);
        }
    };

    stage(0, 0);
    CP_COMMIT();
    for (int c = 0; c < NC; ++c) {
        if (c + 1 < NC) {
            stage((c + 1) & 1, c + 1);
            CP_COMMIT();
            CP_WAIT1();
        } else {
            CP_WAIT0();
        }
        __syncthreads();
        compute(c & 1);
        __syncthreads();
    }

    // epilogue: standard m16n8 D layout
    const int g  = lane >> 2;
    const int tq = lane & 3;

    auto emit = [&](int m, int n, float v) {
        if (MODE == 1) {
            if (n < N_SP) {
                v += (m < 256) ? bias0[m] : bias1[m - 256];
                const __nv_bfloat16 h = __float2bfloat16(v);
                outhi[(size_t)n * 512 + m] = h;
                outlo[(size_t)n * 512 + m] = __float2bfloat16(v - __bfloat162float(h));
            }
        } else if (MODE == 2) {
            if (n < N_SP && m < C_MID)
                outf[(size_t)n * C_MID + m] = fmaxf(v + bias0[m] + bias1[m], 0.f);
        } else if (MODE == 3) {
            if (n < R_ROIS) {
                v = fmaxf(v + bias0[m], 0.f);
                const __nv_bfloat16 h = __float2bfloat16(v);
                outhi[(size_t)n * FC1_DIM + m] = h;
                outlo[(size_t)n * FC1_DIM + m] = __float2bfloat16(v - __bfloat162float(h));
            }
        } else {
            if (n < R_ROIS) {
                if (m < LOC_DIM)
                    outf[(size_t)n * LOC_DIM + m] = v + bias0[m];
                else if (m < LOC_DIM + SCORE_DIM)
                    outf[(size_t)R_ROIS * LOC_DIM + (size_t)n * SCORE_DIM + (m - LOC_DIM)]
                        = v + bias1[m - LOC_DIM];
            }
        }
    };

#pragma unroll
    for (int im = 0; im < 2; ++im) {
        const int mA = mBase + wm * 32 + im * 16 + g;
        const int mB = mA + 8;
#pragma unroll
        for (int in = 0; in < 4; ++in) {
            const int n0 = nBase + wn * 32 + in * 8 + tq * 2;
            const float* dd = acc[im][in];
            emit(mA, n0, dd[0]);
            emit(mA, n0 + 1, dd[1]);
            emit(mB, n0, dd[2]);
            emit(mB, n0 + 1, dd[3]);
        }
    }
}

// ---------------------------------------------------------------------------
// PSROI align max pooling; reads hT [n][490], writes flat bf16 hi/lo [r][512]
// ---------------------------------------------------------------------------
__global__ void psroi_kernel(const float* __restrict__ hT,
                             const float* __restrict__ rois,
                             __nv_bfloat16* __restrict__ fhi,
                             __nv_bfloat16* __restrict__ flo)
{
    const int idx = blockIdx.x * blockDim.x + threadIdx.x;
    if (idx >= R_ROIS * C_MID) return;
    const int r  = idx / C_MID;
    const int c  = idx % C_MID;
    const int gw = c % 7;
    const int gh = (c / 7) % 7;

    const float x1 = rois[r * 4 + 0] * 0.0625f;
    const float y1 = rois[r * 4 + 1] * 0.0625f;
    const float x2 = rois[r * 4 + 2] * 0.0625f;
    const float y2 = rois[r * 4 + 3] * 0.0625f;
    const float bw = (x2 - x1) * (1.f / 7.f);
    const float bh = (y2 - y1) * (1.f / 7.f);

    float best = -1e30f;
#pragma unroll
    for (int sy = 0; sy < 2; ++sy) {
        float ys = y1 + ((float)gh + (sy + 0.5f) * 0.5f) * bh;
        ys = fminf(fmaxf(ys, 0.f), (float)(H_SP - 1));
        const float y0f = floorf(ys);
        const float ly  = ys - y0f;
        const int iy0 = (int)y0f;
        const int iy1 = min(iy0 + 1, H_SP - 1);
#pragma unroll
        for (int sx = 0; sx < 2; ++sx) {
            float xs = x1 + ((float)gw + (sx + 0.5f) * 0.5f) * bw;
            xs = fminf(fmaxf(xs, 0.f), (float)(W_SP - 1));
            const float x0f = floorf(xs);
            const float lx  = xs - x0f;
            const int ix0 = (int)x0f;
            const int ix1 = min(ix0 + 1, W_SP - 1);
            const float v00 = hT[(size_t)(iy0 * W_SP + ix0) * C_MID + c];
            const float v01 = hT[(size_t)(iy0 * W_SP + ix1) * C_MID + c];
            const float v10 = hT[(size_t)(iy1 * W_SP + ix0) * C_MID + c];
            const float v11 = hT[(size_t)(iy1 * W_SP + ix1) * C_MID + c];
            const float v = (1.f - ly) * ((1.f - lx) * v00 + lx * v01)
                          + ly        * ((1.f - lx) * v10 + lx * v11);
            best = fmaxf(best, v);
        }
    }
    const __nv_bfloat16 h = __float2bfloat16(best);
    fhi[(size_t)r * KFC + c] = h;
    flo[(size_t)r * KFC + c] = __float2bfloat16(best - __bfloat162float(h));
}

// ---------------------------------------------------------------------------
// Launch
// ---------------------------------------------------------------------------
extern "C" void kernel_launch(void* const* d_in, const int* in_sizes, int n_in,
                              void* d_out, int out_size)
{
    const float* x         = (const float*)d_in[0];
    const float* rois      = (const float*)d_in[1];
    const float* w_col_max = (const float*)d_in[2];
    const float* b_col_max = (const float*)d_in[3];
    const float* w_col     = (const float*)d_in[4];
    const float* b_col     = (const float*)d_in[5];
    const float* w_row_max = (const float*)d_in[6];
    const float* b_row_max = (const float*)d_in[7];
    const float* w_row     = (const float*)d_in[8];
    const float* b_row     = (const float*)d_in[9];
    const float* fc1_w     = (const float*)d_in[10];
    const float* fc1_b     = (const float*)d_in[11];
    const float* score_w   = (const float*)d_in[12];
    const float* score_b   = (const float*)d_in[13];
    const float* loc_w     = (const float*)d_in[14];
    const float* loc_b     = (const float*)d_in[15];
    float* out = (float*)d_out;

    __nv_bfloat16 *w1hi, *w1lo, *w2hi, *w2lo, *xthi, *xtlo, *y1thi, *y1tlo;
    __nv_bfloat16 *flathi, *flatlo, *fcwhi, *fcwlo, *fc1hi, *fc1lo, *hwhi, *hwlo;
    float *hT;
    cudaGetSymbolAddress((void**)&w1hi,   g_w1hi);
    cudaGetSymbolAddress((void**)&w1lo,   g_w1lo);
    cudaGetSymbolAddress((void**)&w2hi,   g_w2hi);
    cudaGetSymbolAddress((void**)&w2lo,   g_w2lo);
    cudaGetSymbolAddress((void**)&xthi,   g_xthi);
    cudaGetSymbolAddress((void**)&xtlo,   g_xtlo);
    cudaGetSymbolAddress((void**)&y1thi,  g_y1thi);
    cudaGetSymbolAddress((void**)&y1tlo,  g_y1tlo);
    cudaGetSymbolAddress((void**)&hT,     g_hT);
    cudaGetSymbolAddress((void**)&flathi, g_flathi);
    cudaGetSymbolAddress((void**)&flatlo, g_flatlo);
    cudaGetSymbolAddress((void**)&fcwhi,  g_fcwhi);
    cudaGetSymbolAddress((void**)&fcwlo,  g_fcwlo);
    cudaGetSymbolAddress((void**)&fc1hi,  g_fc1hi);
    cudaGetSymbolAddress((void**)&fc1lo,  g_fc1lo);
    cudaGetSymbolAddress((void**)&hwhi,   g_hwhi);
    cudaGetSymbolAddress((void**)&hwlo,   g_hwlo);

    cudaFuncSetAttribute(mma_gemm<1>, cudaFuncAttributeMaxDynamicSharedMemorySize, DYN_SMEM);
    cudaFuncSetAttribute(mma_gemm<2>, cudaFuncAttributeMaxDynamicSharedMemorySize, DYN_SMEM);
    cudaFuncSetAttribute(mma_gemm<3>, cudaFuncAttributeMaxDynamicSharedMemorySize, DYN_SMEM);
    cudaFuncSetAttribute(mma_gemm<4>, cudaFuncAttributeMaxDynamicSharedMemorySize, DYN_SMEM);

    // Prep: layout transform + bf16 hi/lo split
    prep_w1<<<512, 256>>>(w_col_max, w_row_max, w1hi, w1lo);
    prep_w2<<<dim3(490, 2), 256>>>(w_col, w_row, w2hi, w2lo);
    prep_xt<<<dim3(118, 64), 256>>>(x, xthi, xtlo);
    prep_fcw<<<(FC1_DIM * C_MID + 255) / 256, 256>>>(fc1_w, fcwhi, fcwlo);
    prep_hw<<<((LOC_DIM + SCORE_DIM) * FC1_DIM + 255) / 256, 256>>>(loc_w, score_w, hwhi, hwlo);

    // conv1 (both 2048->256 branches, M=512): 59 x 4 = 236 CTAs
    mma_gemm<1><<<dim3(59, 4), 256, DYN_SMEM>>>(
        w1hi, w1lo, xthi, xtlo, b_col_max, b_row_max, y1thi, y1tlo, nullptr);

    // conv2 (sum of both 256->490 branches + relu): 59 x 4
    mma_gemm<2><<<dim3(59, 4), 256, DYN_SMEM>>>(
        w2hi, w2lo, y1thi, y1tlo, b_col, b_row, nullptr, nullptr, hT);

    // PSROI align max -> flat bf16 hi/lo [1000][512]
    psroi_kernel<<<(R_ROIS * C_MID + 255) / 256, 256>>>(hT, rois, flathi, flatlo);

    // fc1 = relu(flat @ fc1_w^T + b): M=2048, N=1024, K=512 -> 16 x 16
    mma_gemm<3><<<dim3(16, 16), 256, DYN_SMEM>>>(
        fcwhi, fcwlo, flathi, flatlo, fc1_b, nullptr, fc1hi, fc1lo, nullptr);

    // heads fused: M=512 (324 loc + 81 score + pad), N=1024, K=2048 -> 16 x 4
    mma_gemm<4><<<dim3(16, 4), 256, DYN_SMEM>>>(
        hwhi, hwlo, fc1hi, fc1lo, loc_b, score_b, nullptr, nullptr, out);
}

// round 11
// speedup vs baseline: 1.2244x; 1.2244x over previous
#include <cuda_runtime.h>
#include <cuda_bf16.h>
#include <stdint.h>
#include <math.h>

// ---------------------------------------------------------------------------
// Problem constants
// ---------------------------------------------------------------------------
#define H_SP 50
#define W_SP 75
#define N_SP 3750
#define R_ROIS 1000
#define C_MID 490
#define FC1_DIM 2048
#define LOC_DIM 324
#define SCORE_DIM 81
#define K1 30720            // conv1 GEMM K (15 taps * 2048 ic)
#define K2 7680             // conv2 GEMM K (2 branches * 15 taps * 256 ic)
#define OC1 512
#define KFC 512             // fc1 K (490 padded)
#define NPAD 1024           // roi rows padded
#define NPART (N_SP * 512)  // one split-K partial slice

// smem staging (R7-proven): Ahi/Alo/Bhi/Blo, 128 rows x 32 bf16, row pad 80B
#define ROWB  80
#define ARRB  (128 * ROWB)          // 10240
#define STAGE (4 * ARRB)            // 40960
#define DYN_SMEM (2 * STAGE)        // 81920 (double buffer)

// ---------------------------------------------------------------------------
// Scratch (device globals, zero-initialized; padding regions never written)
// ---------------------------------------------------------------------------
__device__ __nv_bfloat16 g_w1hi[OC1 * K1], g_w1lo[OC1 * K1];
__device__ __nv_bfloat16 g_w2hi[OC1 * K2], g_w2lo[OC1 * K2];   // rows 490..511 zero
__device__ __nv_bfloat16 g_xthi[N_SP * 2048], g_xtlo[N_SP * 2048];
__device__ __nv_bfloat16 g_y1thi[N_SP * 512], g_y1tlo[N_SP * 512];
__device__ float g_part[2 * NPART];                            // split-K partials
__device__ float g_hT[N_SP * C_MID];
__device__ __nv_bfloat16 g_flathi[NPAD * KFC], g_flatlo[NPAD * KFC];     // cols 490+ zero
__device__ __nv_bfloat16 g_fcwhi[FC1_DIM * KFC], g_fcwlo[FC1_DIM * KFC];
__device__ __nv_bfloat16 g_fc1hi[NPAD * FC1_DIM], g_fc1lo[NPAD * FC1_DIM]; // rows 1000+ zero
__device__ __nv_bfloat16 g_hwhi[512 * FC1_DIM], g_hwlo[512 * FC1_DIM];   // rows 405+ zero

// ---------------------------------------------------------------------------
// PTX helpers (base-sm_100-safe: cp.async / ldmatrix / mma.sync)
// ---------------------------------------------------------------------------
__device__ __forceinline__ uint32_t smem_u32(const void* p) {
    uint32_t a;
    asm("{ .reg .u64 t; cvta.to.shared.u64 t, %1; cvt.u32.u64 %0, t; }"
        : "=r"(a) : "l"(p));
    return a;
}
__device__ __forceinline__ void cpa16(uint32_t dst, const void* src, uint32_t sz) {
    asm volatile("cp.async.ca.shared.global [%0], [%1], 16, %2;"
                 :: "r"(dst), "l"(src), "r"(sz));
}
#define CP_COMMIT() asm volatile("cp.async.commit_group;" ::: "memory")
#define CP_WAIT1()  asm volatile("cp.async.wait_group 1;" ::: "memory")
#define CP_WAIT0()  asm volatile("cp.async.wait_group 0;" ::: "memory")

#define LDM_X4(r, addr) \
    asm volatile("ldmatrix.sync.aligned.m8n8.x4.shared.b16 {%0,%1,%2,%3}, [%4];" \
        : "=r"((r)[0]), "=r"((r)[1]), "=r"((r)[2]), "=r"((r)[3]) : "r"(addr))

#define MMA_BF16(d, a, b) \
    asm volatile("mma.sync.aligned.m16n8k16.row.col.f32.bf16.bf16.f32 " \
        "{%0,%1,%2,%3}, {%4,%5,%6,%7}, {%8,%9}, {%0,%1,%2,%3};" \
        : "+f"((d)[0]), "+f"((d)[1]), "+f"((d)[2]), "+f"((d)[3]) \
        : "r"((a)[0]), "r"((a)[1]), "r"((a)[2]), "r"((a)[3]), "r"((b)[0]), "r"((b)[1]))

// ---------------------------------------------------------------------------
// Prep kernels: layout transform + bf16 hi/lo split
// ---------------------------------------------------------------------------
__global__ void prep_w1(const float* __restrict__ wcm, const float* __restrict__ wrm,
                        __nv_bfloat16* __restrict__ hi, __nv_bfloat16* __restrict__ lo)
{
    __shared__ float tile[256 * 15];
    const int oc = blockIdx.x;
    const int t  = threadIdx.x;
    const float* src = (oc < 256) ? (wcm + (size_t)oc * K1)
                                  : (wrm + (size_t)(oc - 256) * K1);
    for (int ic0 = 0; ic0 < 2048; ic0 += 256) {
        for (int i = t; i < 256 * 15; i += 256) tile[i] = src[ic0 * 15 + i];
        __syncthreads();
        for (int j = t; j < 256 * 15; j += 256) {
            const int tap = j >> 8;
            const int ic  = j & 255;
            const float v = tile[ic * 15 + tap];
            const __nv_bfloat16 h = __float2bfloat16(v);
            const size_t idx = (size_t)oc * K1 + tap * 2048 + ic0 + ic;
            hi[idx] = h;
            lo[idx] = __float2bfloat16(v - __bfloat162float(h));
        }
        __syncthreads();
    }
}

__global__ void prep_w2(const float* __restrict__ wcol, const float* __restrict__ wrow,
                        __nv_bfloat16* __restrict__ hi, __nv_bfloat16* __restrict__ lo)
{
    __shared__ float tile[256 * 15];
    const int oc = blockIdx.x;   // 0..489
    const int b  = blockIdx.y;   // 0: col (1x15), 1: row (15x1)
    const int t  = threadIdx.x;
    const float* src = (b == 0 ? wcol : wrow) + (size_t)oc * 3840;
    for (int i = t; i < 256 * 15; i += 256) tile[i] = src[i];
    __syncthreads();
    for (int j = t; j < 256 * 15; j += 256) {
        const int tap = j >> 8;
        const int ic  = j & 255;
        const float v = tile[ic * 15 + tap];
        const __nv_bfloat16 h = __float2bfloat16(v);
        const size_t idx = (size_t)oc * K2 + b * 3840 + tap * 256 + ic;
        hi[idx] = h;
        lo[idx] = __float2bfloat16(v - __bfloat162float(h));
    }
}

__global__ void prep_xt(const float* __restrict__ x,
                        __nv_bfloat16* __restrict__ hi, __nv_bfloat16* __restrict__ lo)
{
    __shared__ float tile[32][33];
    const int bi = blockIdx.x;            // n tiles (118)
    const int bj = blockIdx.y;            // ic tiles (64)
    const int tx = threadIdx.x & 31;
    const int ty = threadIdx.x >> 5;      // 0..7
#pragma unroll
    for (int r = 0; r < 4; ++r) {
        const int ic = bj * 32 + ty + r * 8;
        const int n  = bi * 32 + tx;
        tile[ty + r * 8][tx] = (n < N_SP) ? x[(size_t)ic * N_SP + n] : 0.f;
    }
    __syncthreads();
#pragma unroll
    for (int r = 0; r < 4; ++r) {
        const int n  = bi * 32 + ty + r * 8;
        const int ic = bj * 32 + tx;
        if (n < N_SP) {
            const float v = tile[tx][ty + r * 8];
            const __nv_bfloat16 h = __float2bfloat16(v);
            hi[(size_t)n * 2048 + ic] = h;
            lo[(size_t)n * 2048 + ic] = __float2bfloat16(v - __bfloat162float(h));
        }
    }
}

// fc1_w [2048][490] -> [2048][512] hi/lo (pad cols zero)
__global__ void prep_fcw(const float* __restrict__ w,
                         __nv_bfloat16* __restrict__ hi, __nv_bfloat16* __restrict__ lo)
{
    const int idx = blockIdx.x * blockDim.x + threadIdx.x;
    if (idx >= FC1_DIM * C_MID) return;
    const int m = idx / C_MID;
    const int k = idx % C_MID;
    const float v = w[idx];
    const __nv_bfloat16 h = __float2bfloat16(v);
    hi[(size_t)m * KFC + k] = h;
    lo[(size_t)m * KFC + k] = __float2bfloat16(v - __bfloat162float(h));
}

// loc_w [324][2048] + score_w [81][2048] -> combined [512][2048] hi/lo
__global__ void prep_hw(const float* __restrict__ locw, const float* __restrict__ scow,
                        __nv_bfloat16* __restrict__ hi, __nv_bfloat16* __restrict__ lo)
{
    const int idx = blockIdx.x * blockDim.x + threadIdx.x;
    if (idx >= (LOC_DIM + SCORE_DIM) * FC1_DIM) return;
    const int m = idx / FC1_DIM;
    const int k = idx % FC1_DIM;
    const float v = (m < LOC_DIM) ? locw[(size_t)m * FC1_DIM + k]
                                  : scow[(size_t)(m - LOC_DIM) * FC1_DIM + k];
    const __nv_bfloat16 h = __float2bfloat16(v);
    hi[(size_t)m * FC1_DIM + k] = h;
    lo[(size_t)m * FC1_DIM + k] = __float2bfloat16(v - __bfloat162float(h));
}

// ---------------------------------------------------------------------------
// Unified GEMM on mma.sync (bf16 hi/lo 3-way split, fp32 acc).
// Block 128(M) x 128(N), K chunks of 32, cp.async double buffer, 8 warps
// in 4x2 (m x n), warp tile 32x64 (R7-proven addressing).
// SPLIT>1: blockIdx.z selects a K slice; fp32 partial written to `part`.
//
// MODE 1: conv1. A=w1 [512][K1], B=XT [3750][2048], h/w shift by mBase.
// MODE 2: conv2. A=w2 [512][K2], B=Y1T [3750][512], k-seg branch/shift.
// MODE 3: fc1.   A=fcw [2048][512], B=flat [1024][512] -> relu+bias, bf16 hi/lo.
// MODE 4: heads. A=hw [512][2048],  B=fc1 [1024][2048] -> d_out.
// ---------------------------------------------------------------------------
template<int MODE, int SPLIT>
__global__ __launch_bounds__(256, 2) void mma_gemm(
    const __nv_bfloat16* __restrict__ Ahi, const __nv_bfloat16* __restrict__ Alo,
    const __nv_bfloat16* __restrict__ Bhi, const __nv_bfloat16* __restrict__ Blo,
    const float* __restrict__ bias0, const float* __restrict__ bias1,
    __nv_bfloat16* __restrict__ outhi, __nv_bfloat16* __restrict__ outlo,
    float* __restrict__ outf)
{
    constexpr int KTOT = (MODE == 1) ? K1 : (MODE == 2) ? K2 : (MODE == 3) ? KFC : FC1_DIM;
    constexpr int LDB  = (MODE == 1) ? 2048 : (MODE == 2) ? 512 : (MODE == 3) ? KFC : FC1_DIM;
    constexpr int KS   = KTOT / SPLIT;
    constexpr int NC   = KS / 32;

    extern __shared__ char smem[];
    const uint32_t sbase = smem_u32(smem);

    const int t    = threadIdx.x;
    const int wid  = t >> 5;
    const int lane = t & 31;
    const int wm   = wid >> 1;        // 0..3 (m)
    const int wn   = wid & 1;         // 0..1 (n)
    const int mBase = blockIdx.y * 128;
    const int nBase = blockIdx.x * 128;
    const int kbase = blockIdx.z * KS;
    const bool mode0_c1 = (MODE == 1) && (mBase < 256);

    // staging: 512 virtual rows over 256 threads (arr = v>>7, row = v&127)
    int arrv[2], rowv[2], nrv[2], w0v[2];
#pragma unroll
    for (int h = 0; h < 2; ++h) {
        const int v = t + h * 256;
        arrv[h] = v >> 7;
        rowv[h] = v & 127;
        nrv[h]  = nBase + rowv[h];
        w0v[h]  = nrv[h] % W_SP;
    }

    float acc[2][8][4];
#pragma unroll
    for (int i = 0; i < 2; ++i)
#pragma unroll
        for (int j = 0; j < 8; ++j)
#pragma unroll
            for (int q = 0; q < 4; ++q) acc[i][j][q] = 0.f;

    auto stage = [&](int buf, int c) {
        const int k0 = kbase + c * 32;
        int d = 0, coloff = k0;
        bool mode0 = false;
        if (MODE == 1) {
            const int tap = k0 >> 11;
            coloff = k0 & 2047;
            mode0  = mode0_c1;
            d = tap - 7;
        } else if (MODE == 2) {
            const int br  = (k0 >= 3840) ? 1 : 0;
            const int rem = k0 - br * 3840;
            const int tap = rem >> 8;
            coloff = br * 256 + (rem & 255);
            mode0  = (br == 1);
            d = tap - 7;
        }
        const int off = mode0 ? d * W_SP : d;
        const uint32_t sb = sbase + buf * STAGE;

#pragma unroll
        for (int h = 0; h < 2; ++h) {
            const int arr = arrv[h];
            const int row = rowv[h];
            const uint32_t dst = sb + arr * ARRB + row * ROWB;
            const char* src;
            uint32_t sz = 16;
            if (arr == 0) {
                src = (const char*)(Ahi + (size_t)(mBase + row) * KTOT + k0);
            } else if (arr == 1) {
                src = (const char*)(Alo + (size_t)(mBase + row) * KTOT + k0);
            } else {
                const int nr = nrv[h];
                long ns = nr;
                if (MODE <= 2) {
                    bool ok;
                    if (mode0) ok = (nr < N_SP) && ((unsigned)(nr + off) < (unsigned)N_SP);
                    else       ok = (nr < N_SP) && ((unsigned)(w0v[h] + d) < (unsigned)W_SP);
                    ns = ok ? (long)nr + off : 0;
                    sz = ok ? 16u : 0u;
                }
                src = (const char*)(((arr == 2) ? Bhi : Blo) + ns * (long)LDB + coloff);
            }
#pragma unroll
            for (int j = 0; j < 4; ++j) cpa16(dst + j * 16, src + j * 16, sz);
        }
    };

    auto compute = [&](int buf) {
        const uint32_t sb = sbase + buf * STAGE;
        const int lr = lane & 15;
        const int lc = lane >> 4;
#pragma unroll
        for (int k16 = 0; k16 < 32; k16 += 16) {
            const uint32_t kb = (uint32_t)(k16 + lc * 8) * 2;
            uint32_t a_hi[2][4], a_lo[2][4];
#pragma unroll
            for (int im = 0; im < 2; ++im) {
                const uint32_t ad = sb + (uint32_t)(wm * 32 + im * 16 + lr) * ROWB + kb;
                LDM_X4(a_hi[im], ad);
                LDM_X4(a_lo[im], ad + ARRB);
            }
            uint32_t b_hi[8][2], b_lo[8][2];
#pragma unroll
            for (int ib = 0; ib < 4; ++ib) {
                const uint32_t bd = sb + 2 * ARRB
                                  + (uint32_t)(wn * 64 + ib * 16 + lr) * ROWB + kb;
                uint32_t r4[4];
                LDM_X4(r4, bd);
                b_hi[2 * ib][0] = r4[0]; b_hi[2 * ib][1] = r4[2];
                b_hi[2 * ib + 1][0] = r4[1]; b_hi[2 * ib + 1][1] = r4[3];
                LDM_X4(r4, bd + ARRB);
                b_lo[2 * ib][0] = r4[0]; b_lo[2 * ib][1] = r4[2];
                b_lo[2 * ib + 1][0] = r4[1]; b_lo[2 * ib + 1][1] = r4[3];
            }
#pragma unroll
            for (int im = 0; im < 2; ++im)
#pragma unroll
                for (int in = 0; in < 8; ++in) MMA_BF16(acc[im][in], a_hi[im], b_hi[in]);
#pragma unroll
            for (int im = 0; im < 2; ++im)
#pragma unroll
                for (int in = 0; in < 8; ++in) MMA_BF16(acc[im][in], a_hi[im], b_lo[in]);
#pragma unroll
            for (int im = 0; im < 2; ++im)
#pragma unroll
                for (int in = 0; in < 8; ++in) MMA_BF16(acc[im][in], a_lo[im], b_hi[in]);
        }
    };

    stage(0, 0);
    CP_COMMIT();
    for (int c = 0; c < NC; ++c) {
        if (c + 1 < NC) {
            stage((c + 1) & 1, c + 1);
            CP_COMMIT();
            CP_WAIT1();
        } else {
            CP_WAIT0();
        }
        __syncthreads();
        compute(c & 1);
        __syncthreads();
    }

    // epilogue: standard m16n8 D layout
    const int g  = lane >> 2;
    const int tq = lane & 3;
    const size_t pbase = (size_t)blockIdx.z * NPART;

    auto emit = [&](int m, int n, float v) {
        if (MODE <= 2) {
            if (n < N_SP) outf[pbase + (size_t)n * 512 + m] = v;   // fp32 partial
        } else if (MODE == 3) {
            if (n < R_ROIS) {
                v = fmaxf(v + bias0[m], 0.f);
                const __nv_bfloat16 h = __float2bfloat16(v);
                outhi[(size_t)n * FC1_DIM + m] = h;
                outlo[(size_t)n * FC1_DIM + m] = __float2bfloat16(v - __bfloat162float(h));
            }
        } else {
            if (n < R_ROIS) {
                if (m < LOC_DIM)
                    outf[(size_t)n * LOC_DIM + m] = v + bias0[m];
                else if (m < LOC_DIM + SCORE_DIM)
                    outf[(size_t)R_ROIS * LOC_DIM + (size_t)n * SCORE_DIM + (m - LOC_DIM)]
                        = v + bias1[m - LOC_DIM];
            }
        }
    };

#pragma unroll
    for (int im = 0; im < 2; ++im) {
        const int mA = mBase + wm * 32 + im * 16 + g;
        const int mB = mA + 8;
#pragma unroll
        for (int in = 0; in < 8; ++in) {
            const int n0 = nBase + wn * 64 + in * 8 + tq * 2;
            const float* dd = acc[im][in];
            emit(mA, n0, dd[0]);
            emit(mA, n0 + 1, dd[1]);
            emit(mB, n0, dd[2]);
            emit(mB, n0 + 1, dd[3]);
        }
    }
}

// ---------------------------------------------------------------------------
// Split-K combines (deterministic fixed-order adds)
// ---------------------------------------------------------------------------
__global__ void combine1(const float* __restrict__ part,
                         const float* __restrict__ b0, const float* __restrict__ b1,
                         __nv_bfloat16* __restrict__ hi, __nv_bfloat16* __restrict__ lo)
{
    const int idx = blockIdx.x * blockDim.x + threadIdx.x;
    if (idx >= NPART) return;
    const int m = idx & 511;
    const float v = part[idx] + part[NPART + idx] + ((m < 256) ? b0[m] : b1[m - 256]);
    const __nv_bfloat16 h = __float2bfloat16(v);
    hi[idx] = h;
    lo[idx] = __float2bfloat16(v - __bfloat162float(h));
}

__global__ void combine2(const float* __restrict__ part,
                         const float* __restrict__ b0, const float* __restrict__ b1,
                         float* __restrict__ hT)
{
    const int idx = blockIdx.x * blockDim.x + threadIdx.x;
    if (idx >= NPART) return;
    const int m = idx & 511;
    if (m >= C_MID) return;
    const int n = idx >> 9;
    const float v = part[idx] + part[NPART + idx] + b0[m] + b1[m];
    hT[(size_t)n * C_MID + m] = fmaxf(v, 0.f);
}

// ---------------------------------------------------------------------------
// PSROI align max pooling; reads hT [n][490], writes flat bf16 hi/lo [r][512]
// ---------------------------------------------------------------------------
__global__ void psroi_kernel(const float* __restrict__ hT,
                             const float* __restrict__ rois,
                             __nv_bfloat16* __restrict__ fhi,
                             __nv_bfloat16* __restrict__ flo)
{
    const int idx = blockIdx.x * blockDim.x + threadIdx.x;
    if (idx >= R_ROIS * C_MID) return;
    const int r  = idx / C_MID;
    const int c  = idx % C_MID;
    const int gw = c % 7;
    const int gh = (c / 7) % 7;

    const float x1 = rois[r * 4 + 0] * 0.0625f;
    const float y1 = rois[r * 4 + 1] * 0.0625f;
    const float x2 = rois[r * 4 + 2] * 0.0625f;
    const float y2 = rois[r * 4 + 3] * 0.0625f;
    const float bw = (x2 - x1) * (1.f / 7.f);
    const float bh = (y2 - y1) * (1.f / 7.f);

    float best = -1e30f;
#pragma unroll
    for (int sy = 0; sy < 2; ++sy) {
        float ys = y1 + ((float)gh + (sy + 0.5f) * 0.5f) * bh;
        ys = fminf(fmaxf(ys, 0.f), (float)(H_SP - 1));
        const float y0f = floorf(ys);
        const float ly  = ys - y0f;
        const int iy0 = (int)y0f;
        const int iy1 = min(iy0 + 1, H_SP - 1);
#pragma unroll
        for (int sx = 0; sx < 2; ++sx) {
            float xs = x1 + ((float)gw + (sx + 0.5f) * 0.5f) * bw;
            xs = fminf(fmaxf(xs, 0.f), (float)(W_SP - 1));
            const float x0f = floorf(xs);
            const float lx  = xs - x0f;
            const int ix0 = (int)x0f;
            const int ix1 = min(ix0 + 1, W_SP - 1);
            const float v00 = hT[(size_t)(iy0 * W_SP + ix0) * C_MID + c];
            const float v01 = hT[(size_t)(iy0 * W_SP + ix1) * C_MID + c];
            const float v10 = hT[(size_t)(iy1 * W_SP + ix0) * C_MID + c];
            const float v11 = hT[(size_t)(iy1 * W_SP + ix1) * C_MID + c];
            const float v = (1.f - ly) * ((1.f - lx) * v00 + lx * v01)
                          + ly        * ((1.f - lx) * v10 + lx * v11);
            best = fmaxf(best, v);
        }
    }
    const __nv_bfloat16 h = __float2bfloat16(best);
    fhi[(size_t)r * KFC + c] = h;
    flo[(size_t)r * KFC + c] = __float2bfloat16(best - __bfloat162float(h));
}

// ---------------------------------------------------------------------------
// Launch
// ---------------------------------------------------------------------------
extern "C" void kernel_launch(void* const* d_in, const int* in_sizes, int n_in,
                              void* d_out, int out_size)
{
    const float* x         = (const float*)d_in[0];
    const float* rois      = (const float*)d_in[1];
    const float* w_col_max = (const float*)d_in[2];
    const float* b_col_max = (const float*)d_in[3];
    const float* w_col     = (const float*)d_in[4];
    const float* b_col     = (const float*)d_in[5];
    const float* w_row_max = (const float*)d_in[6];
    const float* b_row_max = (const float*)d_in[7];
    const float* w_row     = (const float*)d_in[8];
    const float* b_row     = (const float*)d_in[9];
    const float* fc1_w     = (const float*)d_in[10];
    const float* fc1_b     = (const float*)d_in[11];
    const float* score_w   = (const float*)d_in[12];
    const float* score_b   = (const float*)d_in[13];
    const float* loc_w     = (const float*)d_in[14];
    const float* loc_b     = (const float*)d_in[15];
    float* out = (float*)d_out;

    __nv_bfloat16 *w1hi, *w1lo, *w2hi, *w2lo, *xthi, *xtlo, *y1thi, *y1tlo;
    __nv_bfloat16 *flathi, *flatlo, *fcwhi, *fcwlo, *fc1hi, *fc1lo, *hwhi, *hwlo;
    float *hT, *part;
    cudaGetSymbolAddress((void**)&w1hi,   g_w1hi);
    cudaGetSymbolAddress((void**)&w1lo,   g_w1lo);
    cudaGetSymbolAddress((void**)&w2hi,   g_w2hi);
    cudaGetSymbolAddress((void**)&w2lo,   g_w2lo);
    cudaGetSymbolAddress((void**)&xthi,   g_xthi);
    cudaGetSymbolAddress((void**)&xtlo,   g_xtlo);
    cudaGetSymbolAddress((void**)&y1thi,  g_y1thi);
    cudaGetSymbolAddress((void**)&y1tlo,  g_y1tlo);
    cudaGetSymbolAddress((void**)&hT,     g_hT);
    cudaGetSymbolAddress((void**)&part,   g_part);
    cudaGetSymbolAddress((void**)&flathi, g_flathi);
    cudaGetSymbolAddress((void**)&flatlo, g_flatlo);
    cudaGetSymbolAddress((void**)&fcwhi,  g_fcwhi);
    cudaGetSymbolAddress((void**)&fcwlo,  g_fcwlo);
    cudaGetSymbolAddress((void**)&fc1hi,  g_fc1hi);
    cudaGetSymbolAddress((void**)&fc1lo,  g_fc1lo);
    cudaGetSymbolAddress((void**)&hwhi,   g_hwhi);
    cudaGetSymbolAddress((void**)&hwlo,   g_hwlo);

    cudaFuncSetAttribute(mma_gemm<1,2>, cudaFuncAttributeMaxDynamicSharedMemorySize, DYN_SMEM);
    cudaFuncSetAttribute(mma_gemm<2,2>, cudaFuncAttributeMaxDynamicSharedMemorySize, DYN_SMEM);
    cudaFuncSetAttribute(mma_gemm<3,1>, cudaFuncAttributeMaxDynamicSharedMemorySize, DYN_SMEM);
    cudaFuncSetAttribute(mma_gemm<4,1>, cudaFuncAttributeMaxDynamicSharedMemorySize, DYN_SMEM);

    // Prep: layout transform + bf16 hi/lo split
    prep_w1<<<512, 256>>>(w_col_max, w_row_max, w1hi, w1lo);
    prep_w2<<<dim3(490, 2), 256>>>(w_col, w_row, w2hi, w2lo);
    prep_xt<<<dim3(118, 64), 256>>>(x, xthi, xtlo);
    prep_fcw<<<(FC1_DIM * C_MID + 255) / 256, 256>>>(fc1_w, fcwhi, fcwlo);
    prep_hw<<<((LOC_DIM + SCORE_DIM) * FC1_DIM + 255) / 256, 256>>>(loc_w, score_w, hwhi, hwlo);

    // conv1: 128x128 tiles, split-K=2 -> 30 x 4 x 2 = 240 CTAs
    mma_gemm<1,2><<<dim3(30, 4, 2), 256, DYN_SMEM>>>(
        w1hi, w1lo, xthi, xtlo, nullptr, nullptr, nullptr, nullptr, part);
    combine1<<<(NPART + 255) / 256, 256>>>(part, b_col_max, b_row_max, y1thi, y1tlo);

    // conv2: split-K=2 -> 240 CTAs
    mma_gemm<2,2><<<dim3(30, 4, 2), 256, DYN_SMEM>>>(
        w2hi, w2lo, y1thi, y1tlo, nullptr, nullptr, nullptr, nullptr, part);
    combine2<<<(NPART + 255) / 256, 256>>>(part, b_col, b_row, hT);

    // PSROI align max -> flat bf16 hi/lo [1000][512]
    psroi_kernel<<<(R_ROIS * C_MID + 255) / 256, 256>>>(hT, rois, flathi, flatlo);

    // fc1 = relu(flat @ fc1_w^T + b): M=2048, N=1024, K=512 -> 8 x 16
    mma_gemm<3,1><<<dim3(8, 16), 256, DYN_SMEM>>>(
        fcwhi, fcwlo, flathi, flatlo, fc1_b, nullptr, fc1hi, fc1lo, nullptr);

    // heads fused: M=512, N=1024, K=2048 -> 8 x 4
    mma_gemm<4,1><<<dim3(8, 4), 256, DYN_SMEM>>>(
        hwhi, hwlo, fc1hi, fc1lo, loc_b, score_b, nullptr, nullptr, out);
}

// round 14
// speedup vs baseline: 1.6263x; 1.3283x over previous
#include <cuda_runtime.h>
#include <cuda_bf16.h>
#include <stdint.h>
#include <math.h>

// ---------------------------------------------------------------------------
// Problem constants
// ---------------------------------------------------------------------------
#define H_SP 50
#define W_SP 75
#define N_SP 3750
#define R_ROIS 1000
#define C_MID 490
#define FC1_DIM 2048
#define LOC_DIM 324
#define SCORE_DIM 81
#define K1 30720            // conv1 GEMM K (15 taps * 2048 ic)
#define K2 7680             // conv2 GEMM K (2 branches * 15 taps * 256 ic)
#define OC1 512
#define KFC 512             // fc1 K (490 padded)
#define NPAD 1024           // roi rows padded
#define NPART (N_SP * 512)  // one split-K partial slice (conv2)

// bf16 smem staging (R11-proven, conv2/fc): 4 arrays, 128 rows x 32 bf16
#define ROWB  80
#define ARRB  (128 * ROWB)          // 10240
#define STAGE (4 * ARRB)            // 40960
#define DYN_SMEM (2 * STAGE)        // 81920

// int8 conv1 staging: A1(128r) A2(128r) B1(64r) B2(64r), rows 64 int8 + pad
#define C1_A1 0
#define C1_A2 (128 * ROWB)
#define C1_B1 (256 * ROWB)
#define C1_B2 (320 * ROWB)
#define C1_STAGE (384 * ROWB)       // 30720
#define C1_SMEM (2 * C1_STAGE)      // 61440

// ---------------------------------------------------------------------------
// Scratch (device globals, zero-initialized; padding regions never written)
// ---------------------------------------------------------------------------
__device__ char g_w1q1[OC1 * K1], g_w1q2[OC1 * K1];            // conv1 W digits
__device__ char g_xq1[N_SP * 2048], g_xq2[N_SP * 2048];        // XT digits
__device__ float g_sa1[OC1];                                   // per-row W scale
__device__ unsigned g_sbxbits;                                 // global |x| max bits
__device__ __nv_bfloat16 g_w2hi[OC1 * K2], g_w2lo[OC1 * K2];   // rows 490..511 zero
__device__ __nv_bfloat16 g_y1thi[N_SP * 512], g_y1tlo[N_SP * 512];
__device__ float g_part[2 * NPART];                            // conv2 split-K partials
__device__ float g_hT[N_SP * C_MID];
__device__ __nv_bfloat16 g_flathi[NPAD * KFC], g_flatlo[NPAD * KFC];
__device__ __nv_bfloat16 g_fcwhi[FC1_DIM * KFC], g_fcwlo[FC1_DIM * KFC];
__device__ __nv_bfloat16 g_fc1hi[NPAD * FC1_DIM], g_fc1lo[NPAD * FC1_DIM];
__device__ __nv_bfloat16 g_hwhi[512 * FC1_DIM], g_hwlo[512 * FC1_DIM];

// ---------------------------------------------------------------------------
// PTX helpers (base-sm_100-safe: cp.async / ldmatrix / mma.sync)
// ---------------------------------------------------------------------------
__device__ __forceinline__ uint32_t smem_u32(const void* p) {
    uint32_t a;
    asm("{ .reg .u64 t; cvta.to.shared.u64 t, %1; cvt.u32.u64 %0, t; }"
        : "=r"(a) : "l"(p));
    return a;
}
__device__ __forceinline__ void cpa16(uint32_t dst, const void* src, uint32_t sz) {
    asm volatile("cp.async.ca.shared.global [%0], [%1], 16, %2;"
                 :: "r"(dst), "l"(src), "r"(sz));
}
#define CP_COMMIT() asm volatile("cp.async.commit_group;" ::: "memory")
#define CP_WAIT1()  asm volatile("cp.async.wait_group 1;" ::: "memory")
#define CP_WAIT0()  asm volatile("cp.async.wait_group 0;" ::: "memory")

#define LDM_X4(r, addr) \
    asm volatile("ldmatrix.sync.aligned.m8n8.x4.shared.b16 {%0,%1,%2,%3}, [%4];" \
        : "=r"((r)[0]), "=r"((r)[1]), "=r"((r)[2]), "=r"((r)[3]) : "r"(addr))

#define MMA_BF16(d, a, b) \
    asm volatile("mma.sync.aligned.m16n8k16.row.col.f32.bf16.bf16.f32 " \
        "{%0,%1,%2,%3}, {%4,%5,%6,%7}, {%8,%9}, {%0,%1,%2,%3};" \
        : "+f"((d)[0]), "+f"((d)[1]), "+f"((d)[2]), "+f"((d)[3]) \
        : "r"((a)[0]), "r"((a)[1]), "r"((a)[2]), "r"((a)[3]), "r"((b)[0]), "r"((b)[1]))

#define MMA_S8(d, a, b) \
    asm volatile("mma.sync.aligned.m16n8k32.row.col.s32.s8.s8.s32 " \
        "{%0,%1,%2,%3}, {%4,%5,%6,%7}, {%8,%9}, {%0,%1,%2,%3};" \
        : "+r"((d)[0]), "+r"((d)[1]), "+r"((d)[2]), "+r"((d)[3]) \
        : "r"((a)[0]), "r"((a)[1]), "r"((a)[2]), "r"((a)[3]), "r"((b)[0]), "r"((b)[1]))

// ---------------------------------------------------------------------------
// Quantization preps (conv1 int8 path)
// ---------------------------------------------------------------------------
__global__ void prep_xmax(const float* __restrict__ x, unsigned* __restrict__ bits)
{
    __shared__ float red[256];
    float m = 0.f;
    for (int i = blockIdx.x * 256 + threadIdx.x; i < 2048 * N_SP; i += gridDim.x * 256)
        m = fmaxf(m, fabsf(x[i]));
    red[threadIdx.x] = m;
    __syncthreads();
    for (int s = 128; s > 0; s >>= 1) {
        if (threadIdx.x < s) red[threadIdx.x] = fmaxf(red[threadIdx.x], red[threadIdx.x + s]);
        __syncthreads();
    }
    if (threadIdx.x == 0) atomicMax(bits, __float_as_uint(red[0]));
}

__global__ void prep_wmax1(const float* __restrict__ wcm, const float* __restrict__ wrm,
                           float* __restrict__ sa)
{
    __shared__ float red[256];
    const int oc = blockIdx.x;
    const int t  = threadIdx.x;
    const float* src = (oc < 256) ? (wcm + (size_t)oc * K1)
                                  : (wrm + (size_t)(oc - 256) * K1);
    float m = 0.f;
    for (int i = t; i < K1; i += 256) m = fmaxf(m, fabsf(src[i]));
    red[t] = m;
    __syncthreads();
    for (int s = 128; s > 0; s >>= 1) {
        if (t < s) red[t] = fmaxf(red[t], red[t + s]);
        __syncthreads();
    }
    if (t == 0) sa[oc] = fmaxf(red[0], 1e-30f) * (1.f / 127.f);
}

__device__ __forceinline__ void quant2(float v, char& q1, char& q2)
{
    const float r = rintf(v);
    q1 = (char)(int)r;
    q2 = (char)(int)rintf((v - r) * 128.f);
}

// conv1 weights [oc][ic][tap] -> int8 digits K-major [oc][tap*2048+ic]
__global__ void prep_w1q(const float* __restrict__ wcm, const float* __restrict__ wrm,
                         const float* __restrict__ sa,
                         char* __restrict__ q1, char* __restrict__ q2)
{
    __shared__ float tile[256 * 15];
    const int oc = blockIdx.x;
    const int t  = threadIdx.x;
    const float inv = 1.f / sa[oc];
    const float* src = (oc < 256) ? (wcm + (size_t)oc * K1)
                                  : (wrm + (size_t)(oc - 256) * K1);
    for (int ic0 = 0; ic0 < 2048; ic0 += 256) {
        for (int i = t; i < 256 * 15; i += 256) tile[i] = src[ic0 * 15 + i];
        __syncthreads();
        for (int j = t; j < 256 * 15; j += 256) {
            const int tap = j >> 8;
            const int ic  = j & 255;
            const float v = tile[ic * 15 + tap] * inv;
            char d1, d2;
            quant2(v, d1, d2);
            const size_t idx = (size_t)oc * K1 + tap * 2048 + ic0 + ic;
            q1[idx] = d1;
            q2[idx] = d2;
        }
        __syncthreads();
    }
}

// x [2048][3750] -> XT int8 digits [3750][2048], global scale
__global__ void prep_xtq(const float* __restrict__ x, const unsigned* __restrict__ bits,
                         char* __restrict__ q1, char* __restrict__ q2)
{
    __shared__ float tile[32][33];
    const float inv = 127.f / __uint_as_float(*bits);
    const int bi = blockIdx.x;            // n tiles (118)
    const int bj = blockIdx.y;            // ic tiles (64)
    const int tx = threadIdx.x & 31;
    const int ty = threadIdx.x >> 5;
#pragma unroll
    for (int r = 0; r < 4; ++r) {
        const int ic = bj * 32 + ty + r * 8;
        const int n  = bi * 32 + tx;
        tile[ty + r * 8][tx] = (n < N_SP) ? x[(size_t)ic * N_SP + n] : 0.f;
    }
    __syncthreads();
#pragma unroll
    for (int r = 0; r < 4; ++r) {
        const int n  = bi * 32 + ty + r * 8;
        const int ic = bj * 32 + tx;
        if (n < N_SP) {
            char d1, d2;
            quant2(tile[tx][ty + r * 8] * inv, d1, d2);
            q1[(size_t)n * 2048 + ic] = d1;
            q2[(size_t)n * 2048 + ic] = d2;
        }
    }
}

// ---------------------------------------------------------------------------
// bf16 preps (conv2 / fc path — unchanged from R11)
// ---------------------------------------------------------------------------
__global__ void prep_w2(const float* __restrict__ wcol, const float* __restrict__ wrow,
                        __nv_bfloat16* __restrict__ hi, __nv_bfloat16* __restrict__ lo)
{
    __shared__ float tile[256 * 15];
    const int oc = blockIdx.x;
    const int b  = blockIdx.y;
    const int t  = threadIdx.x;
    const float* src = (b == 0 ? wcol : wrow) + (size_t)oc * 3840;
    for (int i = t; i < 256 * 15; i += 256) tile[i] = src[i];
    __syncthreads();
    for (int j = t; j < 256 * 15; j += 256) {
        const int tap = j >> 8;
        const int ic  = j & 255;
        const float v = tile[ic * 15 + tap];
        const __nv_bfloat16 h = __float2bfloat16(v);
        const size_t idx = (size_t)oc * K2 + b * 3840 + tap * 256 + ic;
        hi[idx] = h;
        lo[idx] = __float2bfloat16(v - __bfloat162float(h));
    }
}

__global__ void prep_fcw(const float* __restrict__ w,
                         __nv_bfloat16* __restrict__ hi, __nv_bfloat16* __restrict__ lo)
{
    const int idx = blockIdx.x * blockDim.x + threadIdx.x;
    if (idx >= FC1_DIM * C_MID) return;
    const int m = idx / C_MID;
    const int k = idx % C_MID;
    const float v = w[idx];
    const __nv_bfloat16 h = __float2bfloat16(v);
    hi[(size_t)m * KFC + k] = h;
    lo[(size_t)m * KFC + k] = __float2bfloat16(v - __bfloat162float(h));
}

__global__ void prep_hw(const float* __restrict__ locw, const float* __restrict__ scow,
                        __nv_bfloat16* __restrict__ hi, __nv_bfloat16* __restrict__ lo)
{
    const int idx = blockIdx.x * blockDim.x + threadIdx.x;
    if (idx >= (LOC_DIM + SCORE_DIM) * FC1_DIM) return;
    const int m = idx / FC1_DIM;
    const int k = idx % FC1_DIM;
    const float v = (m < LOC_DIM) ? locw[(size_t)m * FC1_DIM + k]
                                  : scow[(size_t)(m - LOC_DIM) * FC1_DIM + k];
    const __nv_bfloat16 h = __float2bfloat16(v);
    hi[(size_t)m * FC1_DIM + k] = h;
    lo[(size_t)m * FC1_DIM + k] = __float2bfloat16(v - __bfloat162float(h));
}

// ---------------------------------------------------------------------------
// conv1 on IMMA m16n8k32 (int8 two-digit, int32 acc).
// Block 128(M) x 64(N), 8 warps 4x2, warp tile 32x32, K chunks of 64.
// D = sA[m]*SBX*(P11 + (A1B2 + A2B1)/128) + bias -> y1t bf16 hi/lo.
// ---------------------------------------------------------------------------
__global__ __launch_bounds__(256, 2) void conv1_imma(
    const char* __restrict__ A1g, const char* __restrict__ A2g,
    const char* __restrict__ B1g, const char* __restrict__ B2g,
    const float* __restrict__ sa, const unsigned* __restrict__ sbx_bits,
    const float* __restrict__ bias0, const float* __restrict__ bias1,
    __nv_bfloat16* __restrict__ outhi, __nv_bfloat16* __restrict__ outlo)
{
    constexpr int NC = K1 / 64;   // 480 chunks
    extern __shared__ char smem[];
    const uint32_t sbase = smem_u32(smem);

    const int t    = threadIdx.x;
    const int wid  = t >> 5;
    const int lane = t & 31;
    const int wm   = wid >> 1;        // 0..3
    const int wn   = wid & 1;         // 0..1
    const int mBase = blockIdx.y * 128;
    const int nBase = blockIdx.x * 64;
    const bool mode0 = (mBase < 256);  // h-shift branch

    int accP[2][4][4], accC[2][4][4];
#pragma unroll
    for (int i = 0; i < 2; ++i)
#pragma unroll
        for (int j = 0; j < 4; ++j)
#pragma unroll
            for (int q = 0; q < 4; ++q) { accP[i][j][q] = 0; accC[i][j][q] = 0; }

    auto stage = [&](int buf, int c) {
        const int k0 = c * 64;
        const int tap = k0 >> 11;
        const int coloff = k0 & 2047;
        const int d = tap - 7;
        const int off = mode0 ? d * W_SP : d;
        const uint32_t sb = sbase + buf * C1_STAGE;
#pragma unroll
        for (int v = t; v < 384; v += 256) {
            uint32_t dst;
            const char* src;
            uint32_t sz = 16;
            if (v < 256) {
                const int row = v & 127;
                dst = sb + ((v < 128) ? C1_A1 : C1_A2) + row * ROWB;
                src = ((v < 128) ? A1g : A2g) + (size_t)(mBase + row) * K1 + k0;
            } else {
                const int row = (v < 320) ? v - 256 : v - 320;
                const int nr  = nBase + row;
                dst = sb + ((v < 320) ? C1_B1 : C1_B2) + row * ROWB;
                bool ok;
                if (mode0) ok = (nr < N_SP) && ((unsigned)(nr + off) < (unsigned)N_SP);
                else       ok = (nr < N_SP) && ((unsigned)(nr % W_SP + d) < (unsigned)W_SP);
                const long ns = ok ? (long)nr + off : 0;
                src = ((v < 320) ? B1g : B2g) + ns * 2048 + coloff;
                sz = ok ? 16u : 0u;
            }
#pragma unroll
            for (int j = 0; j < 4; ++j) cpa16(dst + j * 16, src + j * 16, sz);
        }
    };

    auto compute = [&](int buf) {
        const uint32_t sb = sbase + buf * C1_STAGE;
        const int rin = (lane & 7) + ((lane >> 3) & 1) * 8;
        const int kpl = (lane >> 4) * 16;
#pragma unroll
        for (int j = 0; j < 2; ++j) {
            const uint32_t ko = (uint32_t)(j * 32) + kpl;
            uint32_t a1f[2][4], a2f[2][4];
#pragma unroll
            for (int im = 0; im < 2; ++im) {
                const uint32_t ra = (uint32_t)(wm * 32 + im * 16 + rin) * ROWB + ko;
                LDM_X4(a1f[im], sb + C1_A1 + ra);
                LDM_X4(a2f[im], sb + C1_A2 + ra);
            }
            uint32_t b1f[4][2], b2f[4][2];
#pragma unroll
            for (int ib = 0; ib < 2; ++ib) {
                const uint32_t rb = (uint32_t)(wn * 32 + ib * 16 + rin) * ROWB + ko;
                uint32_t r4[4];
                LDM_X4(r4, sb + C1_B1 + rb);
                b1f[2 * ib][0] = r4[0]; b1f[2 * ib][1] = r4[2];
                b1f[2 * ib + 1][0] = r4[1]; b1f[2 * ib + 1][1] = r4[3];
                LDM_X4(r4, sb + C1_B2 + rb);
                b2f[2 * ib][0] = r4[0]; b2f[2 * ib][1] = r4[2];
                b2f[2 * ib + 1][0] = r4[1]; b2f[2 * ib + 1][1] = r4[3];
            }
#pragma unroll
            for (int im = 0; im < 2; ++im)
#pragma unroll
                for (int in = 0; in < 4; ++in) MMA_S8(accP[im][in], a1f[im], b1f[in]);
#pragma unroll
            for (int im = 0; im < 2; ++im)
#pragma unroll
                for (int in = 0; in < 4; ++in) MMA_S8(accC[im][in], a1f[im], b2f[in]);
#pragma unroll
            for (int im = 0; im < 2; ++im)
#pragma unroll
                for (int in = 0; in < 4; ++in) MMA_S8(accC[im][in], a2f[im], b1f[in]);
        }
    };

    stage(0, 0);
    CP_COMMIT();
    for (int c = 0; c < NC; ++c) {
        if (c + 1 < NC) {
            stage((c + 1) & 1, c + 1);
            CP_COMMIT();
            CP_WAIT1();
        } else {
            CP_WAIT0();
        }
        __syncthreads();
        compute(c & 1);
        __syncthreads();
    }

    // epilogue: scales + bias, emit y1t bf16 hi/lo
    const int g  = lane >> 2;
    const int tq = lane & 3;
    const float sbx = __uint_as_float(*sbx_bits) * (1.f / 127.f);

    auto emit = [&](int m, int n, float v) {
        if (n < N_SP) {
            const __nv_bfloat16 h = __float2bfloat16(v);
            outhi[(size_t)n * 512 + m] = h;
            outlo[(size_t)n * 512 + m] = __float2bfloat16(v - __bfloat162float(h));
        }
    };

#pragma unroll
    for (int im = 0; im < 2; ++im) {
        const int mA = mBase + wm * 32 + im * 16 + g;
        const int mB = mA + 8;
        const float fA = sa[mA] * sbx;
        const float fB = sa[mB] * sbx;
        const float bA = (mA < 256) ? bias0[mA] : bias1[mA - 256];
        const float bB = (mB < 256) ? bias0[mB] : bias1[mB - 256];
#pragma unroll
        for (int in = 0; in < 4; ++in) {
            const int n0 = nBase + wn * 32 + in * 8 + tq * 2;
            const int* dP = accP[im][in];
            const int* dC = accC[im][in];
            emit(mA, n0,     ((float)dP[0] + (float)dC[0] * (1.f / 128.f)) * fA + bA);
            emit(mA, n0 + 1, ((float)dP[1] + (float)dC[1] * (1.f / 128.f)) * fA + bA);
            emit(mB, n0,     ((float)dP[2] + (float)dC[2] * (1.f / 128.f)) * fB + bB);
            emit(mB, n0 + 1, ((float)dP[3] + (float)dC[3] * (1.f / 128.f)) * fB + bB);
        }
    }
}

// ---------------------------------------------------------------------------
// Unified bf16 GEMM (R11-proven) for conv2 / fc1 / heads.
// Block 128x128, warp 32x64, K chunks of 32, double buffer.
// ---------------------------------------------------------------------------
template<int MODE, int SPLIT>
__global__ __launch_bounds__(256, 2) void mma_gemm(
    const __nv_bfloat16* __restrict__ Ahi, const __nv_bfloat16* __restrict__ Alo,
    const __nv_bfloat16* __restrict__ Bhi, const __nv_bfloat16* __restrict__ Blo,
    const float* __restrict__ bias0, const float* __restrict__ bias1,
    __nv_bfloat16* __restrict__ outhi, __nv_bfloat16* __restrict__ outlo,
    float* __restrict__ outf)
{
    constexpr int KTOT = (MODE == 2) ? K2 : (MODE == 3) ? KFC : FC1_DIM;
    constexpr int LDB  = (MODE == 2) ? 512 : (MODE == 3) ? KFC : FC1_DIM;
    constexpr int KS   = KTOT / SPLIT;
    constexpr int NC   = KS / 32;

    extern __shared__ char smem[];
    const uint32_t sbase = smem_u32(smem);

    const int t    = threadIdx.x;
    const int wid  = t >> 5;
    const int lane = t & 31;
    const int wm   = wid >> 1;
    const int wn   = wid & 1;
    const int mBase = blockIdx.y * 128;
    const int nBase = blockIdx.x * 128;
    const int kbase = blockIdx.z * KS;

    int arrv[2], rowv[2], nrv[2], w0v[2];
#pragma unroll
    for (int h = 0; h < 2; ++h) {
        const int v = t + h * 256;
        arrv[h] = v >> 7;
        rowv[h] = v & 127;
        nrv[h]  = nBase + rowv[h];
        w0v[h]  = nrv[h] % W_SP;
    }

    float acc[2][8][4];
#pragma unroll
    for (int i = 0; i < 2; ++i)
#pragma unroll
        for (int j = 0; j < 8; ++j)
#pragma unroll
            for (int q = 0; q < 4; ++q) acc[i][j][q] = 0.f;

    auto stage = [&](int buf, int c) {
        const int k0 = kbase + c * 32;
        int d = 0, coloff = k0;
        bool mode0 = false;
        if (MODE == 2) {
            const int br  = (k0 >= 3840) ? 1 : 0;
            const int rem = k0 - br * 3840;
            const int tap = rem >> 8;
            coloff = br * 256 + (rem & 255);
            mode0  = (br == 1);
            d = tap - 7;
        }
        const int off = mode0 ? d * W_SP : d;
        const uint32_t sb = sbase + buf * STAGE;

#pragma unroll
        for (int h = 0; h < 2; ++h) {
            const int arr = arrv[h];
            const int row = rowv[h];
            const uint32_t dst = sb + arr * ARRB + row * ROWB;
            const char* src;
            uint32_t sz = 16;
            if (arr == 0) {
                src = (const char*)(Ahi + (size_t)(mBase + row) * KTOT + k0);
            } else if (arr == 1) {
                src = (const char*)(Alo + (size_t)(mBase + row) * KTOT + k0);
            } else {
                const int nr = nrv[h];
                long ns = nr;
                if (MODE == 2) {
                    bool ok;
                    if (mode0) ok = (nr < N_SP) && ((unsigned)(nr + off) < (unsigned)N_SP);
                    else       ok = (nr < N_SP) && ((unsigned)(w0v[h] + d) < (unsigned)W_SP);
                    ns = ok ? (long)nr + off : 0;
                    sz = ok ? 16u : 0u;
                }
                src = (const char*)(((arr == 2) ? Bhi : Blo) + ns * (long)LDB + coloff);
            }
#pragma unroll
            for (int j = 0; j < 4; ++j) cpa16(dst + j * 16, src + j * 16, sz);
        }
    };

    auto compute = [&](int buf) {
        const uint32_t sb = sbase + buf * STAGE;
        const int lr = lane & 15;
        const int lc = lane >> 4;
#pragma unroll
        for (int k16 = 0; k16 < 32; k16 += 16) {
            const uint32_t kb = (uint32_t)(k16 + lc * 8) * 2;
            uint32_t a_hi[2][4], a_lo[2][4];
#pragma unroll
            for (int im = 0; im < 2; ++im) {
                const uint32_t ad = sb + (uint32_t)(wm * 32 + im * 16 + lr) * ROWB + kb;
                LDM_X4(a_hi[im], ad);
                LDM_X4(a_lo[im], ad + ARRB);
            }
            uint32_t b_hi[8][2], b_lo[8][2];
#pragma unroll
            for (int ib = 0; ib < 4; ++ib) {
                const uint32_t bd = sb + 2 * ARRB
                                  + (uint32_t)(wn * 64 + ib * 16 + lr) * ROWB + kb;
                uint32_t r4[4];
                LDM_X4(r4, bd);
                b_hi[2 * ib][0] = r4[0]; b_hi[2 * ib][1] = r4[2];
                b_hi[2 * ib + 1][0] = r4[1]; b_hi[2 * ib + 1][1] = r4[3];
                LDM_X4(r4, bd + ARRB);
                b_lo[2 * ib][0] = r4[0]; b_lo[2 * ib][1] = r4[2];
                b_lo[2 * ib + 1][0] = r4[1]; b_lo[2 * ib + 1][1] = r4[3];
            }
#pragma unroll
            for (int im = 0; im < 2; ++im)
#pragma unroll
                for (int in = 0; in < 8; ++in) MMA_BF16(acc[im][in], a_hi[im], b_hi[in]);
#pragma unroll
            for (int im = 0; im < 2; ++im)
#pragma unroll
                for (int in = 0; in < 8; ++in) MMA_BF16(acc[im][in], a_hi[im], b_lo[in]);
#pragma unroll
            for (int im = 0; im < 2; ++im)
#pragma unroll
                for (int in = 0; in < 8; ++in) MMA_BF16(acc[im][in], a_lo[im], b_hi[in]);
        }
    };

    stage(0, 0);
    CP_COMMIT();
    for (int c = 0; c < NC; ++c) {
        if (c + 1 < NC) {
            stage((c + 1) & 1, c + 1);
            CP_COMMIT();
            CP_WAIT1();
        } else {
            CP_WAIT0();
        }
        __syncthreads();
        compute(c & 1);
        __syncthreads();
    }

    const int g  = lane >> 2;
    const int tq = lane & 3;
    const size_t pbase = (size_t)blockIdx.z * NPART;

    auto emit = [&](int m, int n, float v) {
        if (MODE == 2) {
            if (n < N_SP) outf[pbase + (size_t)n * 512 + m] = v;
        } else if (MODE == 3) {
            if (n < R_ROIS) {
                v = fmaxf(v + bias0[m], 0.f);
                const __nv_bfloat16 h = __float2bfloat16(v);
                outhi[(size_t)n * FC1_DIM + m] = h;
                outlo[(size_t)n * FC1_DIM + m] = __float2bfloat16(v - __bfloat162float(h));
            }
        } else {
            if (n < R_ROIS) {
                if (m < LOC_DIM)
                    outf[(size_t)n * LOC_DIM + m] = v + bias0[m];
                else if (m < LOC_DIM + SCORE_DIM)
                    outf[(size_t)R_ROIS * LOC_DIM + (size_t)n * SCORE_DIM + (m - LOC_DIM)]
                        = v + bias1[m - LOC_DIM];
            }
        }
    };

#pragma unroll
    for (int im = 0; im < 2; ++im) {
        const int mA = mBase + wm * 32 + im * 16 + g;
        const int mB = mA + 8;
#pragma unroll
        for (int in = 0; in < 8; ++in) {
            const int n0 = nBase + wn * 64 + in * 8 + tq * 2;
            const float* dd = acc[im][in];
            emit(mA, n0, dd[0]);
            emit(mA, n0 + 1, dd[1]);
            emit(mB, n0, dd[2]);
            emit(mB, n0 + 1, dd[3]);
        }
    }
}

// conv2 split-K combine
__global__ void combine2(const float* __restrict__ part,
                         const float* __restrict__ b0, const float* __restrict__ b1,
                         float* __restrict__ hT)
{
    const int idx = blockIdx.x * blockDim.x + threadIdx.x;
    if (idx >= NPART) return;
    const int m = idx & 511;
    if (m >= C_MID) return;
    const int n = idx >> 9;
    const float v = part[idx] + part[NPART + idx] + b0[m] + b1[m];
    hT[(size_t)n * C_MID + m] = fmaxf(v, 0.f);
}

// ---------------------------------------------------------------------------
// PSROI align max pooling -> flat bf16 hi/lo [r][512]
// ---------------------------------------------------------------------------
__global__ void psroi_kernel(const float* __restrict__ hT,
                             const float* __restrict__ rois,
                             __nv_bfloat16* __restrict__ fhi,
                             __nv_bfloat16* __restrict__ flo)
{
    const int idx = blockIdx.x * blockDim.x + threadIdx.x;
    if (idx >= R_ROIS * C_MID) return;
    const int r  = idx / C_MID;
    const int c  = idx % C_MID;
    const int gw = c % 7;
    const int gh = (c / 7) % 7;

    const float x1 = rois[r * 4 + 0] * 0.0625f;
    const float y1 = rois[r * 4 + 1] * 0.0625f;
    const float x2 = rois[r * 4 + 2] * 0.0625f;
    const float y2 = rois[r * 4 + 3] * 0.0625f;
    const float bw = (x2 - x1) * (1.f / 7.f);
    const float bh = (y2 - y1) * (1.f / 7.f);

    float best = -1e30f;
#pragma unroll
    for (int sy = 0; sy < 2; ++sy) {
        float ys = y1 + ((float)gh + (sy + 0.5f) * 0.5f) * bh;
        ys = fminf(fmaxf(ys, 0.f), (float)(H_SP - 1));
        const float y0f = floorf(ys);
        const float ly  = ys - y0f;
        const int iy0 = (int)y0f;
        const int iy1 = min(iy0 + 1, H_SP - 1);
#pragma unroll
        for (int sx = 0; sx < 2; ++sx) {
            float xs = x1 + ((float)gw + (sx + 0.5f) * 0.5f) * bw;
            xs = fminf(fmaxf(xs, 0.f), (float)(W_SP - 1));
            const float x0f = floorf(xs);
            const float lx  = xs - x0f;
            const int ix0 = (int)x0f;
            const int ix1 = min(ix0 + 1, W_SP - 1);
            const float v00 = hT[(size_t)(iy0 * W_SP + ix0) * C_MID + c];
            const float v01 = hT[(size_t)(iy0 * W_SP + ix1) * C_MID + c];
            const float v10 = hT[(size_t)(iy1 * W_SP + ix0) * C_MID + c];
            const float v11 = hT[(size_t)(iy1 * W_SP + ix1) * C_MID + c];
            const float v = (1.f - ly) * ((1.f - lx) * v00 + lx * v01)
                          + ly        * ((1.f - lx) * v10 + lx * v11);
            best = fmaxf(best, v);
        }
    }
    const __nv_bfloat16 h = __float2bfloat16(best);
    fhi[(size_t)r * KFC + c] = h;
    flo[(size_t)r * KFC + c] = __float2bfloat16(best - __bfloat162float(h));
}

// ---------------------------------------------------------------------------
// Launch
// ---------------------------------------------------------------------------
extern "C" void kernel_launch(void* const* d_in, const int* in_sizes, int n_in,
                              void* d_out, int out_size)
{
    const float* x         = (const float*)d_in[0];
    const float* rois      = (const float*)d_in[1];
    const float* w_col_max = (const float*)d_in[2];
    const float* b_col_max = (const float*)d_in[3];
    const float* w_col     = (const float*)d_in[4];
    const float* b_col     = (const float*)d_in[5];
    const float* w_row_max = (const float*)d_in[6];
    const float* b_row_max = (const float*)d_in[7];
    const float* w_row     = (const float*)d_in[8];
    const float* b_row     = (const float*)d_in[9];
    const float* fc1_w     = (const float*)d_in[10];
    const float* fc1_b     = (const float*)d_in[11];
    const float* score_w   = (const float*)d_in[12];
    const float* score_b   = (const float*)d_in[13];
    const float* loc_w     = (const float*)d_in[14];
    const float* loc_b     = (const float*)d_in[15];
    float* out = (float*)d_out;

    char *w1q1, *w1q2, *xq1, *xq2;
    float *sa1, *hT, *part;
    unsigned* sbxbits;
    __nv_bfloat16 *w2hi, *w2lo, *y1thi, *y1tlo;
    __nv_bfloat16 *flathi, *flatlo, *fcwhi, *fcwlo, *fc1hi, *fc1lo, *hwhi, *hwlo;
    cudaGetSymbolAddress((void**)&w1q1,    g_w1q1);
    cudaGetSymbolAddress((void**)&w1q2,    g_w1q2);
    cudaGetSymbolAddress((void**)&xq1,     g_xq1);
    cudaGetSymbolAddress((void**)&xq2,     g_xq2);
    cudaGetSymbolAddress((void**)&sa1,     g_sa1);
    cudaGetSymbolAddress((void**)&sbxbits, g_sbxbits);
    cudaGetSymbolAddress((void**)&w2hi,    g_w2hi);
    cudaGetSymbolAddress((void**)&w2lo,    g_w2lo);
    cudaGetSymbolAddress((void**)&y1thi,   g_y1thi);
    cudaGetSymbolAddress((void**)&y1tlo,   g_y1tlo);
    cudaGetSymbolAddress((void**)&hT,      g_hT);
    cudaGetSymbolAddress((void**)&part,    g_part);
    cudaGetSymbolAddress((void**)&flathi,  g_flathi);
    cudaGetSymbolAddress((void**)&flatlo,  g_flatlo);
    cudaGetSymbolAddress((void**)&fcwhi,   g_fcwhi);
    cudaGetSymbolAddress((void**)&fcwlo,   g_fcwlo);
    cudaGetSymbolAddress((void**)&fc1hi,   g_fc1hi);
    cudaGetSymbolAddress((void**)&fc1lo,   g_fc1lo);
    cudaGetSymbolAddress((void**)&hwhi,    g_hwhi);
    cudaGetSymbolAddress((void**)&hwlo,    g_hwlo);

    cudaFuncSetAttribute(conv1_imma,   cudaFuncAttributeMaxDynamicSharedMemorySize, C1_SMEM);
    cudaFuncSetAttribute(mma_gemm<2,2>, cudaFuncAttributeMaxDynamicSharedMemorySize, DYN_SMEM);
    cudaFuncSetAttribute(mma_gemm<3,1>, cudaFuncAttributeMaxDynamicSharedMemorySize, DYN_SMEM);
    cudaFuncSetAttribute(mma_gemm<4,1>, cudaFuncAttributeMaxDynamicSharedMemorySize, DYN_SMEM);

    // Quantization preps (conv1) + bf16 preps (conv2/fc)
    prep_xmax<<<256, 256>>>(x, sbxbits);
    prep_wmax1<<<512, 256>>>(w_col_max, w_row_max, sa1);
    prep_xtq<<<dim3(118, 64), 256>>>(x, sbxbits, xq1, xq2);
    prep_w1q<<<512, 256>>>(w_col_max, w_row_max, sa1, w1q1, w1q2);
    prep_w2<<<dim3(490, 2), 256>>>(w_col, w_row, w2hi, w2lo);
    prep_fcw<<<(FC1_DIM * C_MID + 255) / 256, 256>>>(fc1_w, fcwhi, fcwlo);
    prep_hw<<<((LOC_DIM + SCORE_DIM) * FC1_DIM + 255) / 256, 256>>>(loc_w, score_w, hwhi, hwlo);

    // conv1 int8: 128x64 tiles -> 59 x 4 = 236 CTAs, direct epilogue
    conv1_imma<<<dim3(59, 4), 256, C1_SMEM>>>(
        w1q1, w1q2, xq1, xq2, sa1, sbxbits, b_col_max, b_row_max, y1thi, y1tlo);

    // conv2 bf16 split-K=2 (unchanged R11 path)
    mma_gemm<2,2><<<dim3(30, 4, 2), 256, DYN_SMEM>>>(
        w2hi, w2lo, y1thi, y1tlo, nullptr, nullptr, nullptr, nullptr, part);
    combine2<<<(NPART + 255) / 256, 256>>>(part, b_col, b_row, hT);

    // PSROI -> flat bf16 hi/lo
    psroi_kernel<<<(R_ROIS * C_MID + 255) / 256, 256>>>(hT, rois, flathi, flatlo);

    // fc1 + heads (unchanged R11 path)
    mma_gemm<3,1><<<dim3(8, 16), 256, DYN_SMEM>>>(
        fcwhi, fcwlo, flathi, flatlo, fc1_b, nullptr, fc1hi, fc1lo, nullptr);
    mma_gemm<4,1><<<dim3(8, 4), 256, DYN_SMEM>>>(
        hwhi, hwlo, fc1hi, fc1lo, loc_b, score_b, nullptr, nullptr, out);
}

// round 16
// speedup vs baseline: 1.6546x; 1.0174x over previous
#include <cuda_runtime.h>
#include <cuda_bf16.h>
#include <stdint.h>
#include <math.h>

// ---------------------------------------------------------------------------
// Problem constants
// ---------------------------------------------------------------------------
#define H_SP 50
#define W_SP 75
#define N_SP 3750
#define R_ROIS 1000
#define C_MID 490
#define FC1_DIM 2048
#define LOC_DIM 324
#define SCORE_DIM 81
#define K1 30720            // conv1 GEMM K (15 taps * 2048 ic)
#define K2 7680             // conv2 GEMM K (2 branches * 15 taps * 256 ic)
#define OC1 512
#define KFC 512             // fc1 K (490 padded)
#define NPAD 1024           // roi rows padded

// bf16 smem staging (fc path): 4 arrays, 128 rows x 32 bf16, row pad 80B
#define ROWB  80
#define ARRB  (128 * ROWB)          // 10240
#define STAGE (4 * ARRB)            // 40960
#define DYN_SMEM (2 * STAGE)        // 81920

// int8 conv staging: A1(128r) A2(128r) B1(64r) B2(64r), rows 64 int8 + pad
#define C1_A1 0
#define C1_A2 (128 * ROWB)
#define C1_B1 (256 * ROWB)
#define C1_B2 (320 * ROWB)
#define C1_STAGE (384 * ROWB)       // 30720
#define C1_SMEM (3 * C1_STAGE)      // 92160 (triple buffer)

// ---------------------------------------------------------------------------
// Scratch (device globals, zero-initialized; padding regions never written)
// ---------------------------------------------------------------------------
__device__ char g_w1q1[OC1 * K1], g_w1q2[OC1 * K1];            // conv1 W digits
__device__ char g_xq1[N_SP * 2048], g_xq2[N_SP * 2048];        // XT digits
__device__ float g_sa1[OC1];                                   // conv1 per-row W scale
__device__ unsigned g_sbxbits;                                 // global |x| max bits
__device__ char g_w2q1[OC1 * K2], g_w2q2[OC1 * K2];            // conv2 W digits (rows 490+ zero)
__device__ float g_sa2[OC1];                                   // conv2 per-row W scale
__device__ float g_y1f[N_SP * 512];                            // conv1 out fp32
__device__ unsigned g_sy1bits;                                 // global |y1| max bits
__device__ char g_y1q1[N_SP * 512], g_y1q2[N_SP * 512];        // y1 digits
__device__ float g_hT[N_SP * C_MID];
__device__ __nv_bfloat16 g_flathi[NPAD * KFC], g_flatlo[NPAD * KFC];
__device__ __nv_bfloat16 g_fcwhi[FC1_DIM * KFC], g_fcwlo[FC1_DIM * KFC];
__device__ __nv_bfloat16 g_fc1hi[NPAD * FC1_DIM], g_fc1lo[NPAD * FC1_DIM];
__device__ __nv_bfloat16 g_hwhi[512 * FC1_DIM], g_hwlo[512 * FC1_DIM];

// ---------------------------------------------------------------------------
// PTX helpers (base-sm_100-safe: cp.async / ldmatrix / mma.sync)
// ---------------------------------------------------------------------------
__device__ __forceinline__ uint32_t smem_u32(const void* p) {
    uint32_t a;
    asm("{ .reg .u64 t; cvta.to.shared.u64 t, %1; cvt.u32.u64 %0, t; }"
        : "=r"(a) : "l"(p));
    return a;
}
__device__ __forceinline__ void cpa16(uint32_t dst, const void* src, uint32_t sz) {
    asm volatile("cp.async.ca.shared.global [%0], [%1], 16, %2;"
                 :: "r"(dst), "l"(src), "r"(sz));
}
#define CP_COMMIT() asm volatile("cp.async.commit_group;" ::: "memory")
#define CP_WAIT2()  asm volatile("cp.async.wait_group 2;" ::: "memory")
#define CP_WAIT1()  asm volatile("cp.async.wait_group 1;" ::: "memory")
#define CP_WAIT0()  asm volatile("cp.async.wait_group 0;" ::: "memory")

#define LDM_X4(r, addr) \
    asm volatile("ldmatrix.sync.aligned.m8n8.x4.shared.b16 {%0,%1,%2,%3}, [%4];" \
        : "=r"((r)[0]), "=r"((r)[1]), "=r"((r)[2]), "=r"((r)[3]) : "r"(addr))

#define MMA_BF16(d, a, b) \
    asm volatile("mma.sync.aligned.m16n8k16.row.col.f32.bf16.bf16.f32 " \
        "{%0,%1,%2,%3}, {%4,%5,%6,%7}, {%8,%9}, {%0,%1,%2,%3};" \
        : "+f"((d)[0]), "+f"((d)[1]), "+f"((d)[2]), "+f"((d)[3]) \
        : "r"((a)[0]), "r"((a)[1]), "r"((a)[2]), "r"((a)[3]), "r"((b)[0]), "r"((b)[1]))

#define MMA_S8(d, a, b) \
    asm volatile("mma.sync.aligned.m16n8k32.row.col.s32.s8.s8.s32 " \
        "{%0,%1,%2,%3}, {%4,%5,%6,%7}, {%8,%9}, {%0,%1,%2,%3};" \
        : "+r"((d)[0]), "+r"((d)[1]), "+r"((d)[2]), "+r"((d)[3]) \
        : "r"((a)[0]), "r"((a)[1]), "r"((a)[2]), "r"((a)[3]), "r"((b)[0]), "r"((b)[1]))

// ---------------------------------------------------------------------------
// Quantization preps
// ---------------------------------------------------------------------------
__device__ __forceinline__ void quant2(float v, char& q1, char& q2)
{
    const float r = rintf(v);
    q1 = (char)(int)r;
    q2 = (char)(int)rintf((v - r) * 128.f);
}

__global__ void prep_fmax(const float* __restrict__ p, long n, unsigned* __restrict__ bits)
{
    __shared__ float red[256];
    float m = 0.f;
    for (long i = blockIdx.x * 256 + threadIdx.x; i < n; i += (long)gridDim.x * 256)
        m = fmaxf(m, fabsf(p[i]));
    red[threadIdx.x] = m;
    __syncthreads();
    for (int s = 128; s > 0; s >>= 1) {
        if (threadIdx.x < s) red[threadIdx.x] = fmaxf(red[threadIdx.x], red[threadIdx.x + s]);
        __syncthreads();
    }
    if (threadIdx.x == 0) atomicMax(bits, __float_as_uint(red[0]));
}

__global__ void prep_wmax1(const float* __restrict__ wcm, const float* __restrict__ wrm,
                           float* __restrict__ sa)
{
    __shared__ float red[256];
    const int oc = blockIdx.x;
    const int t  = threadIdx.x;
    const float* src = (oc < 256) ? (wcm + (size_t)oc * K1)
                                  : (wrm + (size_t)(oc - 256) * K1);
    float m = 0.f;
    for (int i = t; i < K1; i += 256) m = fmaxf(m, fabsf(src[i]));
    red[t] = m;
    __syncthreads();
    for (int s = 128; s > 0; s >>= 1) {
        if (t < s) red[t] = fmaxf(red[t], red[t + s]);
        __syncthreads();
    }
    if (t == 0) sa[oc] = fmaxf(red[0], 1e-30f) * (1.f / 127.f);
}

__global__ void prep_wmax2(const float* __restrict__ wcol, const float* __restrict__ wrow,
                           float* __restrict__ sa)
{
    __shared__ float red[256];
    const int oc = blockIdx.x;   // 0..489
    const int t  = threadIdx.x;
    float m = 0.f;
    for (int i = t; i < 3840; i += 256) {
        m = fmaxf(m, fabsf(wcol[(size_t)oc * 3840 + i]));
        m = fmaxf(m, fabsf(wrow[(size_t)oc * 3840 + i]));
    }
    red[t] = m;
    __syncthreads();
    for (int s = 128; s > 0; s >>= 1) {
        if (t < s) red[t] = fmaxf(red[t], red[t + s]);
        __syncthreads();
    }
    if (t == 0) sa[oc] = fmaxf(red[0], 1e-30f) * (1.f / 127.f);
}

// conv1 weights [oc][ic][tap] -> int8 digits K-major [oc][tap*2048+ic]
__global__ void prep_w1q(const float* __restrict__ wcm, const float* __restrict__ wrm,
                         const float* __restrict__ sa,
                         char* __restrict__ q1, char* __restrict__ q2)
{
    __shared__ float tile[256 * 15];
    const int oc = blockIdx.x;
    const int t  = threadIdx.x;
    const float inv = 1.f / sa[oc];
    const float* src = (oc < 256) ? (wcm + (size_t)oc * K1)
                                  : (wrm + (size_t)(oc - 256) * K1);
    for (int ic0 = 0; ic0 < 2048; ic0 += 256) {
        for (int i = t; i < 256 * 15; i += 256) tile[i] = src[ic0 * 15 + i];
        __syncthreads();
        for (int j = t; j < 256 * 15; j += 256) {
            const int tap = j >> 8;
            const int ic  = j & 255;
            char d1, d2;
            quant2(tile[ic * 15 + tap] * inv, d1, d2);
            const size_t idx = (size_t)oc * K1 + tap * 2048 + ic0 + ic;
            q1[idx] = d1;
            q2[idx] = d2;
        }
        __syncthreads();
    }
}

// conv2 weights [oc][256][15] -> digits [oc][br*3840 + tap*256 + ic]
__global__ void prep_w2q(const float* __restrict__ wcol, const float* __restrict__ wrow,
                         const float* __restrict__ sa,
                         char* __restrict__ q1, char* __restrict__ q2)
{
    __shared__ float tile[256 * 15];
    const int oc = blockIdx.x;   // 0..489
    const int b  = blockIdx.y;   // 0: col (1x15), 1: row (15x1)
    const int t  = threadIdx.x;
    const float inv = 1.f / sa[oc];
    const float* src = (b == 0 ? wcol : wrow) + (size_t)oc * 3840;
    for (int i = t; i < 256 * 15; i += 256) tile[i] = src[i];
    __syncthreads();
    for (int j = t; j < 256 * 15; j += 256) {
        const int tap = j >> 8;
        const int ic  = j & 255;
        char d1, d2;
        quant2(tile[ic * 15 + tap] * inv, d1, d2);
        const size_t idx = (size_t)oc * K2 + b * 3840 + tap * 256 + ic;
        q1[idx] = d1;
        q2[idx] = d2;
    }
}

// x [2048][3750] -> XT int8 digits [3750][2048], global scale
__global__ void prep_xtq(const float* __restrict__ x, const unsigned* __restrict__ bits,
                         char* __restrict__ q1, char* __restrict__ q2)
{
    __shared__ float tile[32][33];
    const float inv = 127.f / __uint_as_float(*bits);
    const int bi = blockIdx.x;
    const int bj = blockIdx.y;
    const int tx = threadIdx.x & 31;
    const int ty = threadIdx.x >> 5;
#pragma unroll
    for (int r = 0; r < 4; ++r) {
        const int ic = bj * 32 + ty + r * 8;
        const int n  = bi * 32 + tx;
        tile[ty + r * 8][tx] = (n < N_SP) ? x[(size_t)ic * N_SP + n] : 0.f;
    }
    __syncthreads();
#pragma unroll
    for (int r = 0; r < 4; ++r) {
        const int n  = bi * 32 + ty + r * 8;
        const int ic = bj * 32 + tx;
        if (n < N_SP) {
            char d1, d2;
            quant2(tile[tx][ty + r * 8] * inv, d1, d2);
            q1[(size_t)n * 2048 + ic] = d1;
            q2[(size_t)n * 2048 + ic] = d2;
        }
    }
}

// y1 fp32 [n][512] -> digits, global scale
__global__ void prep_y1q(const float* __restrict__ y, const unsigned* __restrict__ bits,
                         char* __restrict__ q1, char* __restrict__ q2)
{
    const float inv = 127.f / __uint_as_float(*bits);
    const int idx = blockIdx.x * blockDim.x + threadIdx.x;
    if (idx >= N_SP * 512) return;
    char d1, d2;
    quant2(y[idx] * inv, d1, d2);
    q1[idx] = d1;
    q2[idx] = d2;
}

// ---------------------------------------------------------------------------
// bf16 preps (fc path)
// ---------------------------------------------------------------------------
__global__ void prep_fcw(const float* __restrict__ w,
                         __nv_bfloat16* __restrict__ hi, __nv_bfloat16* __restrict__ lo)
{
    const int idx = blockIdx.x * blockDim.x + threadIdx.x;
    if (idx >= FC1_DIM * C_MID) return;
    const int m = idx / C_MID;
    const int k = idx % C_MID;
    const float v = w[idx];
    const __nv_bfloat16 h = __float2bfloat16(v);
    hi[(size_t)m * KFC + k] = h;
    lo[(size_t)m * KFC + k] = __float2bfloat16(v - __bfloat162float(h));
}

__global__ void prep_hw(const float* __restrict__ locw, const float* __restrict__ scow,
                        __nv_bfloat16* __restrict__ hi, __nv_bfloat16* __restrict__ lo)
{
    const int idx = blockIdx.x * blockDim.x + threadIdx.x;
    if (idx >= (LOC_DIM + SCORE_DIM) * FC1_DIM) return;
    const int m = idx / FC1_DIM;
    const int k = idx % FC1_DIM;
    const float v = (m < LOC_DIM) ? locw[(size_t)m * FC1_DIM + k]
                                  : scow[(size_t)(m - LOC_DIM) * FC1_DIM + k];
    const __nv_bfloat16 h = __float2bfloat16(v);
    hi[(size_t)m * FC1_DIM + k] = h;
    lo[(size_t)m * FC1_DIM + k] = __float2bfloat16(v - __bfloat162float(h));
}

// ---------------------------------------------------------------------------
// conv on IMMA m16n8k32 (int8 two-digit, int32 acc), 3-stage pipeline.
// Block 128(M) x 64(N), 8 warps 4x2, warp tile 32x32, K chunks of 64.
// D = sA[m]*SB*(P11 + (A1B2 + A2B1)/128) + bias.
// CONV==1: A=w1q [512][K1], B=xq [3750][2048], mBase<256 -> h-shift.
//          out: y1f fp32 [n][512].
// CONV==2: A=w2q [512][K2], B=y1q [3750][512], k-seg selects branch/shift.
//          out: hT fp32 [n][490] = relu(v + b0[m] + b1[m]).
// ---------------------------------------------------------------------------
template<int CONV>
__global__ __launch_bounds__(256, 2) void conv_imma(
    const char* __restrict__ A1g, const char* __restrict__ A2g,
    const char* __restrict__ B1g, const char* __restrict__ B2g,
    const float* __restrict__ sa, const unsigned* __restrict__ sb_bits,
    const float* __restrict__ bias0, const float* __restrict__ bias1,
    float* __restrict__ outf)
{
    constexpr int KTOT = (CONV == 1) ? K1 : K2;
    constexpr int LDB  = (CONV == 1) ? 2048 : 512;
    constexpr int NC   = KTOT / 64;

    extern __shared__ char smem[];
    const uint32_t sbase = smem_u32(smem);

    const int t    = threadIdx.x;
    const int wid  = t >> 5;
    const int lane = t & 31;
    const int wm   = wid >> 1;
    const int wn   = wid & 1;
    const int mBase = blockIdx.y * 128;
    const int nBase = blockIdx.x * 64;
    const bool mode0_c1 = (CONV == 1) && (mBase < 256);

    int accP[2][4][4], accC[2][4][4];
#pragma unroll
    for (int i = 0; i < 2; ++i)
#pragma unroll
        for (int j = 0; j < 4; ++j)
#pragma unroll
            for (int q = 0; q < 4; ++q) { accP[i][j][q] = 0; accC[i][j][q] = 0; }

    auto stage = [&](int buf, int c) {
        const int k0 = c * 64;
        int d, coloff;
        bool mode0;
        if (CONV == 1) {
            const int tap = k0 >> 11;
            coloff = k0 & 2047;
            mode0  = mode0_c1;
            d = tap - 7;
        } else {
            const int br  = (k0 >= 3840) ? 1 : 0;
            const int rem = k0 - br * 3840;
            const int tap = rem >> 8;
            coloff = br * 256 + (rem & 255);
            mode0  = (br == 1);
            d = tap - 7;
        }
        const int off = mode0 ? d * W_SP : d;
        const uint32_t sb = sbase + buf * C1_STAGE;
#pragma unroll
        for (int v = t; v < 384; v += 256) {
            uint32_t dst;
            const char* src;
            uint32_t sz = 16;
            if (v < 256) {
                const int row = v & 127;
                dst = sb + ((v < 128) ? C1_A1 : C1_A2) + row * ROWB;
                src = ((v < 128) ? A1g : A2g) + (size_t)(mBase + row) * KTOT + k0;
            } else {
                const int row = (v < 320) ? v - 256 : v - 320;
                const int nr  = nBase + row;
                dst = sb + ((v < 320) ? C1_B1 : C1_B2) + row * ROWB;
                bool ok;
                if (mode0) ok = (nr < N_SP) && ((unsigned)(nr + off) < (unsigned)N_SP);
                else       ok = (nr < N_SP) && ((unsigned)(nr % W_SP + d) < (unsigned)W_SP);
                const long ns = ok ? (long)nr + off : 0;
                src = ((v < 320) ? B1g : B2g) + ns * LDB + coloff;
                sz = ok ? 16u : 0u;
            }
#pragma unroll
            for (int j = 0; j < 4; ++j) cpa16(dst + j * 16, src + j * 16, sz);
        }
    };

    auto compute = [&](int buf) {
        const uint32_t sb = sbase + buf * C1_STAGE;
        const int rin = (lane & 7) + ((lane >> 3) & 1) * 8;
        const int kpl = (lane >> 4) * 16;
#pragma unroll
        for (int j = 0; j < 2; ++j) {
            const uint32_t ko = (uint32_t)(j * 32) + kpl;
            uint32_t a1f[2][4], a2f[2][4];
#pragma unroll
            for (int im = 0; im < 2; ++im) {
                const uint32_t ra = (uint32_t)(wm * 32 + im * 16 + rin) * ROWB + ko;
                LDM_X4(a1f[im], sb + C1_A1 + ra);
                LDM_X4(a2f[im], sb + C1_A2 + ra);
            }
            uint32_t b1f[4][2], b2f[4][2];
#pragma unroll
            for (int ib = 0; ib < 2; ++ib) {
                const uint32_t rb = (uint32_t)(wn * 32 + ib * 16 + rin) * ROWB + ko;
                uint32_t r4[4];
                LDM_X4(r4, sb + C1_B1 + rb);
                b1f[2 * ib][0] = r4[0]; b1f[2 * ib][1] = r4[2];
                b1f[2 * ib + 1][0] = r4[1]; b1f[2 * ib + 1][1] = r4[3];
                LDM_X4(r4, sb + C1_B2 + rb);
                b2f[2 * ib][0] = r4[0]; b2f[2 * ib][1] = r4[2];
                b2f[2 * ib + 1][0] = r4[1]; b2f[2 * ib + 1][1] = r4[3];
            }
#pragma unroll
            for (int im = 0; im < 2; ++im)
#pragma unroll
                for (int in = 0; in < 4; ++in) MMA_S8(accP[im][in], a1f[im], b1f[in]);
#pragma unroll
            for (int im = 0; im < 2; ++im)
#pragma unroll
                for (int in = 0; in < 4; ++in) MMA_S8(accC[im][in], a1f[im], b2f[in]);
#pragma unroll
            for (int im = 0; im < 2; ++im)
#pragma unroll
                for (int in = 0; in < 4; ++in) MMA_S8(accC[im][in], a2f[im], b1f[in]);
        }
    };

    stage(0, 0); CP_COMMIT();
    stage(1, 1); CP_COMMIT();
    for (int c = 0; c < NC; ++c) {
        if (c + 2 < NC) {
            stage((c + 2) % 3, c + 2);
            CP_COMMIT();
            CP_WAIT2();
        } else if (c + 1 < NC) {
            CP_WAIT1();
        } else {
            CP_WAIT0();
        }
        __syncthreads();
        compute(c % 3);
        __syncthreads();
    }

    // epilogue
    const int g  = lane >> 2;
    const int tq = lane & 3;
    const float sb = __uint_as_float(*sb_bits) * (1.f / 127.f);

    auto emit = [&](int m, int n, float v) {
        if (CONV == 1) {
            if (n < N_SP) outf[(size_t)n * 512 + m] = v;
        } else {
            if (n < N_SP && m < C_MID) outf[(size_t)n * C_MID + m] = fmaxf(v, 0.f);
        }
    };

#pragma unroll
    for (int im = 0; im < 2; ++im) {
        const int mA = mBase + wm * 32 + im * 16 + g;
        const int mB = mA + 8;
        const float fA = sa[mA] * sb;
        const float fB = sa[mB] * sb;
        float bA, bB;
        if (CONV == 1) {
            bA = (mA < 256) ? bias0[mA] : bias1[mA - 256];
            bB = (mB < 256) ? bias0[mB] : bias1[mB - 256];
        } else {
            bA = (mA < C_MID) ? bias0[mA] + bias1[mA] : 0.f;
            bB = (mB < C_MID) ? bias0[mB] + bias1[mB] : 0.f;
        }
#pragma unroll
        for (int in = 0; in < 4; ++in) {
            const int n0 = nBase + wn * 32 + in * 8 + tq * 2;
            const int* dP = accP[im][in];
            const int* dC = accC[im][in];
            emit(mA, n0,     ((float)dP[0] + (float)dC[0] * (1.f / 128.f)) * fA + bA);
            emit(mA, n0 + 1, ((float)dP[1] + (float)dC[1] * (1.f / 128.f)) * fA + bA);
            emit(mB, n0,     ((float)dP[2] + (float)dC[2] * (1.f / 128.f)) * fB + bB);
            emit(mB, n0 + 1, ((float)dP[3] + (float)dC[3] * (1.f / 128.f)) * fB + bB);
        }
    }
}

// ---------------------------------------------------------------------------
// Unified bf16 GEMM for fc1 / heads.
// Block 128x128, warp 32x64, K chunks of 32, double buffer.
// MODE 3: fc1.   A=fcw [2048][512], B=flat [1024][512] -> relu+bias, bf16 hi/lo.
// MODE 4: heads. A=hw [512][2048],  B=fc1 [1024][2048] -> d_out.
// ---------------------------------------------------------------------------
template<int MODE>
__global__ __launch_bounds__(256, 2) void mma_gemm(
    const __nv_bfloat16* __restrict__ Ahi, const __nv_bfloat16* __restrict__ Alo,
    const __nv_bfloat16* __restrict__ Bhi, const __nv_bfloat16* __restrict__ Blo,
    const float* __restrict__ bias0, const float* __restrict__ bias1,
    __nv_bfloat16* __restrict__ outhi, __nv_bfloat16* __restrict__ outlo,
    float* __restrict__ outf)
{
    constexpr int KTOT = (MODE == 3) ? KFC : FC1_DIM;
    constexpr int NC   = KTOT / 32;

    extern __shared__ char smem[];
    const uint32_t sbase = smem_u32(smem);

    const int t    = threadIdx.x;
    const int wid  = t >> 5;
    const int lane = t & 31;
    const int wm   = wid >> 1;
    const int wn   = wid & 1;
    const int mBase = blockIdx.y * 128;
    const int nBase = blockIdx.x * 128;

    int arrv[2], rowv[2];
#pragma unroll
    for (int h = 0; h < 2; ++h) {
        const int v = t + h * 256;
        arrv[h] = v >> 7;
        rowv[h] = v & 127;
    }

    float acc[2][8][4];
#pragma unroll
    for (int i = 0; i < 2; ++i)
#pragma unroll
        for (int j = 0; j < 8; ++j)
#pragma unroll
            for (int q = 0; q < 4; ++q) acc[i][j][q] = 0.f;

    auto stage = [&](int buf, int c) {
        const int k0 = c * 32;
        const uint32_t sb = sbase + buf * STAGE;
#pragma unroll
        for (int h = 0; h < 2; ++h) {
            const int arr = arrv[h];
            const int row = rowv[h];
            const uint32_t dst = sb + arr * ARRB + row * ROWB;
            const char* src;
            if (arr == 0)      src = (const char*)(Ahi + (size_t)(mBase + row) * KTOT + k0);
            else if (arr == 1) src = (const char*)(Alo + (size_t)(mBase + row) * KTOT + k0);
            else if (arr == 2) src = (const char*)(Bhi + (size_t)(nBase + row) * KTOT + k0);
            else               src = (const char*)(Blo + (size_t)(nBase + row) * KTOT + k0);
#pragma unroll
            for (int j = 0; j < 4; ++j) cpa16(dst + j * 16, src + j * 16, 16);
        }
    };

    auto compute = [&](int buf) {
        const uint32_t sb = sbase + buf * STAGE;
        const int lr = lane & 15;
        const int lc = lane >> 4;
#pragma unroll
        for (int k16 = 0; k16 < 32; k16 += 16) {
            const uint32_t kb = (uint32_t)(k16 + lc * 8) * 2;
            uint32_t a_hi[2][4], a_lo[2][4];
#pragma unroll
            for (int im = 0; im < 2; ++im) {
                const uint32_t ad = sb + (uint32_t)(wm * 32 + im * 16 + lr) * ROWB + kb;
                LDM_X4(a_hi[im], ad);
                LDM_X4(a_lo[im], ad + ARRB);
            }
            uint32_t b_hi[8][2], b_lo[8][2];
#pragma unroll
            for (int ib = 0; ib < 4; ++ib) {
                const uint32_t bd = sb + 2 * ARRB
                                  + (uint32_t)(wn * 64 + ib * 16 + lr) * ROWB + kb;
                uint32_t r4[4];
                LDM_X4(r4, bd);
                b_hi[2 * ib][0] = r4[0]; b_hi[2 * ib][1] = r4[2];
                b_hi[2 * ib + 1][0] = r4[1]; b_hi[2 * ib + 1][1] = r4[3];
                LDM_X4(r4, bd + ARRB);
                b_lo[2 * ib][0] = r4[0]; b_lo[2 * ib][1] = r4[2];
                b_lo[2 * ib + 1][0] = r4[1]; b_lo[2 * ib + 1][1] = r4[3];
            }
#pragma unroll
            for (int im = 0; im < 2; ++im)
#pragma unroll
                for (int in = 0; in < 8; ++in) MMA_BF16(acc[im][in], a_hi[im], b_hi[in]);
#pragma unroll
            for (int im = 0; im < 2; ++im)
#pragma unroll
                for (int in = 0; in < 8; ++in) MMA_BF16(acc[im][in], a_hi[im], b_lo[in]);
#pragma unroll
            for (int im = 0; im < 2; ++im)
#pragma unroll
                for (int in = 0; in < 8; ++in) MMA_BF16(acc[im][in], a_lo[im], b_hi[in]);
        }
    };

    stage(0, 0);
    CP_COMMIT();
    for (int c = 0; c < NC; ++c) {
        if (c + 1 < NC) {
            stage((c + 1) & 1, c + 1);
            CP_COMMIT();
            CP_WAIT1();
        } else {
            CP_WAIT0();
        }
        __syncthreads();
        compute(c & 1);
        __syncthreads();
    }

    const int g  = lane >> 2;
    const int tq = lane & 3;

    auto emit = [&](int m, int n, float v) {
        if (MODE == 3) {
            if (n < R_ROIS) {
                v = fmaxf(v + bias0[m], 0.f);
                const __nv_bfloat16 h = __float2bfloat16(v);
                outhi[(size_t)n * FC1_DIM + m] = h;
                outlo[(size_t)n * FC1_DIM + m] = __float2bfloat16(v - __bfloat162float(h));
            }
        } else {
            if (n < R_ROIS) {
                if (m < LOC_DIM)
                    outf[(size_t)n * LOC_DIM + m] = v + bias0[m];
                else if (m < LOC_DIM + SCORE_DIM)
                    outf[(size_t)R_ROIS * LOC_DIM + (size_t)n * SCORE_DIM + (m - LOC_DIM)]
                        = v + bias1[m - LOC_DIM];
            }
        }
    };

#pragma unroll
    for (int im = 0; im < 2; ++im) {
        const int mA = mBase + wm * 32 + im * 16 + g;
        const int mB = mA + 8;
#pragma unroll
        for (int in = 0; in < 8; ++in) {
            const int n0 = nBase + wn * 64 + in * 8 + tq * 2;
            const float* dd = acc[im][in];
            emit(mA, n0, dd[0]);
            emit(mA, n0 + 1, dd[1]);
            emit(mB, n0, dd[2]);
            emit(mB, n0 + 1, dd[3]);
        }
    }
}

// ---------------------------------------------------------------------------
// PSROI align max pooling -> flat bf16 hi/lo [r][512]
// ---------------------------------------------------------------------------
__global__ void psroi_kernel(const float* __restrict__ hT,
                             const float* __restrict__ rois,
                             __nv_bfloat16* __restrict__ fhi,
                             __nv_bfloat16* __restrict__ flo)
{
    const int idx = blockIdx.x * blockDim.x + threadIdx.x;
    if (idx >= R_ROIS * C_MID) return;
    const int r  = idx / C_MID;
    const int c  = idx % C_MID;
    const int gw = c % 7;
    const int gh = (c / 7) % 7;

    const float x1 = rois[r * 4 + 0] * 0.0625f;
    const float y1 = rois[r * 4 + 1] * 0.0625f;
    const float x2 = rois[r * 4 + 2] * 0.0625f;
    const float y2 = rois[r * 4 + 3] * 0.0625f;
    const float bw = (x2 - x1) * (1.f / 7.f);
    const float bh = (y2 - y1) * (1.f / 7.f);

    float best = -1e30f;
#pragma unroll
    for (int sy = 0; sy < 2; ++sy) {
        float ys = y1 + ((float)gh + (sy + 0.5f) * 0.5f) * bh;
        ys = fminf(fmaxf(ys, 0.f), (float)(H_SP - 1));
        const float y0f = floorf(ys);
        const float ly  = ys - y0f;
        const int iy0 = (int)y0f;
        const int iy1 = min(iy0 + 1, H_SP - 1);
#pragma unroll
        for (int sx = 0; sx < 2; ++sx) {
            float xs = x1 + ((float)gw + (sx + 0.5f) * 0.5f) * bw;
            xs = fminf(fmaxf(xs, 0.f), (float)(W_SP - 1));
            const float x0f = floorf(xs);
            const float lx  = xs - x0f;
            const int ix0 = (int)x0f;
            const int ix1 = min(ix0 + 1, W_SP - 1);
            const float v00 = hT[(size_t)(iy0 * W_SP + ix0) * C_MID + c];
            const float v01 = hT[(size_t)(iy0 * W_SP + ix1) * C_MID + c];
            const float v10 = hT[(size_t)(iy1 * W_SP + ix0) * C_MID + c];
            const float v11 = hT[(size_t)(iy1 * W_SP + ix1) * C_MID + c];
            const float v = (1.f - ly) * ((1.f - lx) * v00 + lx * v01)
                          + ly        * ((1.f - lx) * v10 + lx * v11);
            best = fmaxf(best, v);
        }
    }
    const __nv_bfloat16 h = __float2bfloat16(best);
    fhi[(size_t)r * KFC + c] = h;
    flo[(size_t)r * KFC + c] = __float2bfloat16(best - __bfloat162float(h));
}

// ---------------------------------------------------------------------------
// Launch
// ---------------------------------------------------------------------------
extern "C" void kernel_launch(void* const* d_in, const int* in_sizes, int n_in,
                              void* d_out, int out_size)
{
    const float* x         = (const float*)d_in[0];
    const float* rois      = (const float*)d_in[1];
    const float* w_col_max = (const float*)d_in[2];
    const float* b_col_max = (const float*)d_in[3];
    const float* w_col     = (const float*)d_in[4];
    const float* b_col     = (const float*)d_in[5];
    const float* w_row_max = (const float*)d_in[6];
    const float* b_row_max = (const float*)d_in[7];
    const float* w_row     = (const float*)d_in[8];
    const float* b_row     = (const float*)d_in[9];
    const float* fc1_w     = (const float*)d_in[10];
    const float* fc1_b     = (const float*)d_in[11];
    const float* score_w   = (const float*)d_in[12];
    const float* score_b   = (const float*)d_in[13];
    const float* loc_w     = (const float*)d_in[14];
    const float* loc_b     = (const float*)d_in[15];
    float* out = (float*)d_out;

    char *w1q1, *w1q2, *xq1, *xq2, *w2q1, *w2q2, *y1q1, *y1q2;
    float *sa1, *sa2, *y1f, *hT;
    unsigned *sbxbits, *sy1bits;
    __nv_bfloat16 *flathi, *flatlo, *fcwhi, *fcwlo, *fc1hi, *fc1lo, *hwhi, *hwlo;
    cudaGetSymbolAddress((void**)&w1q1,    g_w1q1);
    cudaGetSymbolAddress((void**)&w1q2,    g_w1q2);
    cudaGetSymbolAddress((void**)&xq1,     g_xq1);
    cudaGetSymbolAddress((void**)&xq2,     g_xq2);
    cudaGetSymbolAddress((void**)&sa1,     g_sa1);
    cudaGetSymbolAddress((void**)&sbxbits, g_sbxbits);
    cudaGetSymbolAddress((void**)&w2q1,    g_w2q1);
    cudaGetSymbolAddress((void**)&w2q2,    g_w2q2);
    cudaGetSymbolAddress((void**)&sa2,     g_sa2);
    cudaGetSymbolAddress((void**)&y1f,     g_y1f);
    cudaGetSymbolAddress((void**)&sy1bits, g_sy1bits);
    cudaGetSymbolAddress((void**)&y1q1,    g_y1q1);
    cudaGetSymbolAddress((void**)&y1q2,    g_y1q2);
    cudaGetSymbolAddress((void**)&hT,      g_hT);
    cudaGetSymbolAddress((void**)&flathi,  g_flathi);
    cudaGetSymbolAddress((void**)&flatlo,  g_flatlo);
    cudaGetSymbolAddress((void**)&fcwhi,   g_fcwhi);
    cudaGetSymbolAddress((void**)&fcwlo,   g_fcwlo);
    cudaGetSymbolAddress((void**)&fc1hi,   g_fc1hi);
    cudaGetSymbolAddress((void**)&fc1lo,   g_fc1lo);
    cudaGetSymbolAddress((void**)&hwhi,    g_hwhi);
    cudaGetSymbolAddress((void**)&hwlo,    g_hwlo);

    cudaFuncSetAttribute(conv_imma<1>, cudaFuncAttributeMaxDynamicSharedMemorySize, C1_SMEM);
    cudaFuncSetAttribute(conv_imma<2>, cudaFuncAttributeMaxDynamicSharedMemorySize, C1_SMEM);
    cudaFuncSetAttribute(mma_gemm<3>,  cudaFuncAttributeMaxDynamicSharedMemorySize, DYN_SMEM);
    cudaFuncSetAttribute(mma_gemm<4>,  cudaFuncAttributeMaxDynamicSharedMemorySize, DYN_SMEM);

    // Quantization + bf16 preps
    prep_fmax<<<256, 256>>>(x, (long)2048 * N_SP, sbxbits);
    prep_wmax1<<<512, 256>>>(w_col_max, w_row_max, sa1);
    prep_wmax2<<<490, 256>>>(w_col, w_row, sa2);
    prep_xtq<<<dim3(118, 64), 256>>>(x, sbxbits, xq1, xq2);
    prep_w1q<<<512, 256>>>(w_col_max, w_row_max, sa1, w1q1, w1q2);
    prep_w2q<<<dim3(490, 2), 256>>>(w_col, w_row, sa2, w2q1, w2q2);
    prep_fcw<<<(FC1_DIM * C_MID + 255) / 256, 256>>>(fc1_w, fcwhi, fcwlo);
    prep_hw<<<((LOC_DIM + SCORE_DIM) * FC1_DIM + 255) / 256, 256>>>(loc_w, score_w, hwhi, hwlo);

    // conv1 int8 -> y1f fp32
    conv_imma<1><<<dim3(59, 4), 256, C1_SMEM>>>(
        w1q1, w1q2, xq1, xq2, sa1, sbxbits, b_col_max, b_row_max, y1f);

    // quantize y1 (global scale)
    prep_fmax<<<256, 256>>>(y1f, (long)N_SP * 512, sy1bits);
    prep_y1q<<<(N_SP * 512 + 255) / 256, 256>>>(y1f, sy1bits, y1q1, y1q2);

    // conv2 int8 -> hT fp32 (relu + biases fused)
    conv_imma<2><<<dim3(59, 4), 256, C1_SMEM>>>(
        w2q1, w2q2, y1q1, y1q2, sa2, sy1bits, b_col, b_row, hT);

    // PSROI -> flat bf16 hi/lo
    psroi_kernel<<<(R_ROIS * C_MID + 255) / 256, 256>>>(hT, rois, flathi, flatlo);

    // fc1 + heads (bf16 path)
    mma_gemm<3><<<dim3(8, 16), 256, DYN_SMEM>>>(
        fcwhi, fcwlo, flathi, flatlo, fc1_b, nullptr, fc1hi, fc1lo, nullptr);
    mma_gemm<4><<<dim3(8, 4), 256, DYN_SMEM>>>(
        hwhi, hwlo, fc1hi, fc1lo, loc_b, score_b, nullptr, nullptr, out);
}